// round 7
// baseline (speedup 1.0000x reference)
#include <cuda_runtime.h>
#include <cstdint>

#define NMAX   100000
#define EMAX   600000
#define HDIM   128
#define BCMAX  384

// ---------------- static scratch (no allocations allowed) ----------------
__device__ float g_x     [NMAX * HDIM];     // node features (ping)
__device__ float g_x2    [NMAX * HDIM];     // node features (pong)
__device__ float g_xm    [NMAX * HDIM];     // neighbor-mean of x
__device__ float g_xin   [NMAX * 64];       // packed encoder input (padded 48->64)
__device__ float g_Wcomb [256 * 128];       // rows 0-127: Wu1+A ; rows 128-255: B
__device__ float g_A     [128 * 128];       // Wm_i @ Wu2 (for deg==0 patch)
__device__ float g_cvec  [128];             // b_m @ Wu2
__device__ float g_Wenc  [64 * 128];        // padded encoder weight
__device__ float g_pr    [BCMAX * HDIM];    // pooled_scaled @ Wu3
__device__ int   g_rowptr[NMAX + 1];
__device__ int   g_rowfill[NMAX];
__device__ int   g_deg   [NMAX];
__device__ int   g_csr   [EMAX];
__device__ int   g_ccount[BCMAX];
__device__ int   g_coff  [BCMAX + 1];
__device__ int   g_cfill [BCMAX];
__device__ int   g_cnodes[NMAX];
__device__ int   g_bsum  [64];
__device__ int   g_bsumex[64];
__device__ int   g_srcA  [EMAX];
__device__ int   g_dstA  [EMAX];
__device__ int   g_ccA   [NMAX];
__device__ int   g_flag  [2];
__device__ int   g_dzlist[NMAX];
__device__ int   g_dzcnt [1];

// ---------------- dtype detection ----------------
// int64 little-endian values in [0, N) have every odd int32 word == 0.
__global__ void k_detect(const int* __restrict__ e32, const int* __restrict__ c32,
                         int* flag) {
    int t = threadIdx.x;  // 32 threads
    int ok_e = 1, ok_c = 1;
    for (int i = t; i < 256; i += 32) {
        ok_e &= (e32[2 * i + 1] == 0);
        ok_c &= (c32[2 * i + 1] == 0);
    }
    ok_e = __all_sync(0xffffffffu, ok_e);
    ok_c = __all_sync(0xffffffffu, ok_c);
    if (t == 0) { flag[0] = ok_e; flag[1] = ok_c; }
}

__global__ void k_zero(int* deg, int* ccount, int* dzcnt, int n, int bc) {
    int i = blockIdx.x * blockDim.x + threadIdx.x;
    if (i < n)  deg[i] = 0;
    if (i < bc) ccount[i] = 0;
    if (i == 0) dzcnt[0] = 0;
}

// convert indices to int32 AND histogram in one pass
__global__ void k_convhist(const void* __restrict__ e, const void* __restrict__ cc,
                           int* __restrict__ srcA, int* __restrict__ dstA,
                           int* __restrict__ ccA, const int* __restrict__ flag,
                           int* deg, int* ccount, int E, int n) {
    int i = blockIdx.x * blockDim.x + threadIdx.x;
    int f0 = flag[0], f1 = flag[1];
    if (i < E) {
        int s, d;
        if (f0) {
            const long long* e64 = (const long long*)e;
            s = (int)e64[i]; d = (int)e64[(size_t)E + i];
        } else {
            const int* e32 = (const int*)e;
            s = e32[i]; d = e32[E + i];
        }
        if ((unsigned)s >= (unsigned)n) s = 0;
        if ((unsigned)d >= (unsigned)n) d = 0;
        srcA[i] = s; dstA[i] = d;
        atomicAdd(&deg[d], 1);
    }
    if (i < n) {
        int c = f1 ? (int)((const long long*)cc)[i] : ((const int*)cc)[i];
        if ((unsigned)c >= (unsigned)BCMAX) c = 0;
        ccA[i] = c;
        atomicAdd(&ccount[c], 1);
    }
}

// exclusive scan, 2-level: per-block (4096 elems) scan + block sums
__global__ void k_scan_blocks(const int* __restrict__ in, int* __restrict__ out,
                              int* __restrict__ bsum, int n) {
    __shared__ int sm[1024];
    int t = threadIdx.x;
    int base = blockIdx.x * 4096 + t * 4;
    int v0 = (base + 0 < n) ? in[base + 0] : 0;
    int v1 = (base + 1 < n) ? in[base + 1] : 0;
    int v2 = (base + 2 < n) ? in[base + 2] : 0;
    int v3 = (base + 3 < n) ? in[base + 3] : 0;
    int tot = v0 + v1 + v2 + v3;
    sm[t] = tot; __syncthreads();
    for (int off = 1; off < 1024; off <<= 1) {
        int add = (t >= off) ? sm[t - off] : 0;
        __syncthreads();
        sm[t] += add;
        __syncthreads();
    }
    if (t == 1023) bsum[blockIdx.x] = sm[1023];
    int run = sm[t] - tot;
    if (base + 0 < n) out[base + 0] = run; run += v0;
    if (base + 1 < n) out[base + 1] = run; run += v1;
    if (base + 2 < n) out[base + 2] = run; run += v2;
    if (base + 3 < n) out[base + 3] = run;
}

__global__ void k_scan_small(const int* __restrict__ in, int* __restrict__ out,
                             int* __restrict__ fill, int n, int writeTotal) {
    __shared__ int sm[1024];
    int t = threadIdx.x;
    int v = (t < n) ? in[t] : 0;
    sm[t] = v; __syncthreads();
    for (int off = 1; off < 1024; off <<= 1) {
        int add = (t >= off) ? sm[t - off] : 0;
        __syncthreads();
        sm[t] += add;
        __syncthreads();
    }
    if (t < n) {
        int ex = sm[t] - v;
        out[t] = ex;
        if (fill) fill[t] = ex;
    }
    if (writeTotal && t == 1023) out[n] = sm[1023];
}

// add block offsets AND seed rowfill
__global__ void k_addoff(int* rowptr, int* rowfill, const int* bsumex, int n, int total) {
    int i = blockIdx.x * blockDim.x + threadIdx.x;
    if (i < n) {
        int v = rowptr[i] + bsumex[i >> 12];
        rowptr[i] = v;
        rowfill[i] = v;
    }
    if (i == 0) rowptr[n] = total;
}

__global__ void k_scatter(const int* __restrict__ srcA, const int* __restrict__ dstA,
                          const int* __restrict__ ccA,
                          int* rowfill, int* csr, int* cfill, int* cnodes, int E, int n) {
    int i = blockIdx.x * blockDim.x + threadIdx.x;
    if (i < E) {
        int pos = atomicAdd(&rowfill[dstA[i]], 1);
        if ((unsigned)pos < (unsigned)EMAX) csr[pos] = srcA[i];
    }
    if (i < n) {
        int pos = atomicAdd(&cfill[ccA[i]], 1);
        if ((unsigned)pos < (unsigned)NMAX) cnodes[pos] = i;
    }
}

// build list of deg==0 nodes
__global__ void k_dzlist(const int* __restrict__ rowptr, int* dzlist, int* dzcnt, int n) {
    int i = blockIdx.x * blockDim.x + threadIdx.x;
    if (i < n && rowptr[i + 1] == rowptr[i]) {
        int p = atomicAdd(dzcnt, 1);
        dzlist[p] = i;
    }
}

// ---------------- weight folding ----------------
// Wcomb rows 0-127:  Wu1[k][:] + (Wm_i @ Wu2)[k][:]
// Wcomb rows 128-255: (Wm_j @ Wu2)[k][:]
__global__ void k_fold(const float* __restrict__ W_m, const float* __restrict__ W_u,
                       float* __restrict__ Wcomb, float* __restrict__ A) {
    int k = blockIdx.x;      // 0..127
    int t = threadIdx.x;     // 0..255
    __shared__ float wi[128], wj[128];
    if (t < 128) {
        wi[t] = W_m[k * 128 + t];
        wj[t] = W_m[(128 + k) * 128 + t];
    }
    __syncthreads();
    if (t < 128) {
        float acc = 0.f;
        #pragma unroll 8
        for (int q = 0; q < 128; q++) acc += wi[q] * W_u[(128 + q) * 128 + t];
        A[k * 128 + t] = acc;
        Wcomb[k * 128 + t] = W_u[k * 128 + t] + acc;
    } else {
        int j = t - 128;
        float acc = 0.f;
        #pragma unroll 8
        for (int q = 0; q < 128; q++) acc += wj[q] * W_u[(128 + q) * 128 + j];
        Wcomb[(128 + k) * 128 + j] = acc;
    }
}

__global__ void k_cvec(const float* __restrict__ b_m, const float* __restrict__ W_u,
                       float* __restrict__ cvec) {
    int j = threadIdx.x;
    float acc = 0.f;
    #pragma unroll 8
    for (int k = 0; k < 128; k++) acc += b_m[k] * W_u[(128 + k) * 128 + j];
    cvec[j] = acc;
}

__global__ void k_wenc(const float* __restrict__ W_enc, float* __restrict__ Wenc) {
    int k = blockIdx.x, h = threadIdx.x;
    Wenc[k * 128 + h] = (k < 48) ? W_enc[k * 128 + h] : 0.f;
}

__global__ void k_pack(const float* __restrict__ cf, const float* __restrict__ slf,
                       const float* __restrict__ z, float* __restrict__ xin, int n) {
    int i = blockIdx.x * blockDim.x + threadIdx.x;
    if (i >= n * 64) return;
    int nd = i >> 6, c = i & 63;
    float v;
    if (c < 15)       v = cf[nd * 15 + c];
    else if (c == 15) v = slf[nd];
    else if (c < 48)  v = z[nd * 32 + (c - 16)];
    else              v = 0.f;
    xin[i] = v;
}

// ---------------- tf32 GEMM: C[M,128] = X[M,K] @ W[K,128], fused epilogue ----------------
__device__ __forceinline__ float to_tf32(float x) {
    float r; asm("cvt.rna.tf32.f32 %0, %1;" : "=f"(r) : "f"(x)); return r;
}
__device__ __forceinline__ float lrelu(float u) { return (u > 0.f) ? u : 0.01f * u; }

// KTOT: 64 (encoder, X0 rows of 64) or 256 (layer: X0 rows 0-127, X1 rows 128-255)
// EPI=false: C = X@W + bias
// EPI=true:  u = X0@W[0:128] + X1@W[128:256] + cvec + pr[ccA] + bu ; C = Xres + lrelu(u)
template<int KTOT, bool EPI>
__global__ __launch_bounds__(256) void k_gemm(
    const float* __restrict__ X0, const float* __restrict__ X1,
    const float* __restrict__ W,
    const float* __restrict__ bias,
    const float* __restrict__ Xres, const float* __restrict__ pr,
    const int* __restrict__ ccA, const float* __restrict__ cvec,
    const float* __restrict__ bu,
    float* __restrict__ C, int M) {
    __shared__ float As[128 * 36];
    __shared__ float Bs[32 * 132];
    const int tid = threadIdx.x;
    const int lane = tid & 31, wid = tid >> 5;
    const int wm = wid & 3, wn = wid >> 2;         // wm 0-3, wn 0-1
    const int gid = lane >> 2, tig = lane & 3;
    const int row0 = blockIdx.x * 128;
    float acc[2][8][4];
    #pragma unroll
    for (int mi = 0; mi < 2; mi++)
        #pragma unroll
        for (int ni = 0; ni < 8; ni++)
            #pragma unroll
            for (int q = 0; q < 4; q++) acc[mi][ni][q] = 0.f;

    for (int kb = 0; kb < KTOT; kb += 32) {
        #pragma unroll
        for (int i = 0; i < 4; i++) {
            int f = tid + i * 256;
            int r = f >> 3, c4 = (f & 7) * 4;
            int grow = row0 + r;
            float4 v = make_float4(0.f, 0.f, 0.f, 0.f);
            if (grow < M) {
                if (KTOT == 64) {
                    v = *(const float4*)(X0 + (size_t)grow * 64 + kb + c4);
                } else {
                    if (kb < 128) v = *(const float4*)(X0 + (size_t)grow * 128 + kb + c4);
                    else          v = *(const float4*)(X1 + (size_t)grow * 128 + (kb - 128) + c4);
                }
            }
            float* dst = &As[r * 36 + c4];
            dst[0] = to_tf32(v.x); dst[1] = to_tf32(v.y);
            dst[2] = to_tf32(v.z); dst[3] = to_tf32(v.w);
        }
        #pragma unroll
        for (int i = 0; i < 4; i++) {
            int f = tid + i * 256;
            int k = f >> 5, n4 = (f & 31) * 4;
            float4 v = *(const float4*)(W + (size_t)(kb + k) * 128 + n4);
            float* dst = &Bs[k * 132 + n4];
            dst[0] = to_tf32(v.x); dst[1] = to_tf32(v.y);
            dst[2] = to_tf32(v.z); dst[3] = to_tf32(v.w);
        }
        __syncthreads();
        #pragma unroll
        for (int kk = 0; kk < 4; kk++) {
            const int kc = kk * 8;
            unsigned a[2][4];
            #pragma unroll
            for (int mi = 0; mi < 2; mi++) {
                int rb = wm * 32 + mi * 16;
                a[mi][0] = __float_as_uint(As[(rb + gid    ) * 36 + kc + tig]);
                a[mi][1] = __float_as_uint(As[(rb + gid + 8) * 36 + kc + tig]);
                a[mi][2] = __float_as_uint(As[(rb + gid    ) * 36 + kc + tig + 4]);
                a[mi][3] = __float_as_uint(As[(rb + gid + 8) * 36 + kc + tig + 4]);
            }
            unsigned b[8][2];
            #pragma unroll
            for (int ni = 0; ni < 8; ni++) {
                int cb = wn * 64 + ni * 8 + gid;
                b[ni][0] = __float_as_uint(Bs[(kc + tig    ) * 132 + cb]);
                b[ni][1] = __float_as_uint(Bs[(kc + tig + 4) * 132 + cb]);
            }
            #pragma unroll
            for (int mi = 0; mi < 2; mi++)
                #pragma unroll
                for (int ni = 0; ni < 8; ni++)
                    asm volatile(
                        "mma.sync.aligned.m16n8k8.row.col.f32.tf32.tf32.f32 "
                        "{%0,%1,%2,%3}, {%4,%5,%6,%7}, {%8,%9}, {%0,%1,%2,%3};\n"
                        : "+f"(acc[mi][ni][0]), "+f"(acc[mi][ni][1]),
                          "+f"(acc[mi][ni][2]), "+f"(acc[mi][ni][3])
                        : "r"(a[mi][0]), "r"(a[mi][1]), "r"(a[mi][2]), "r"(a[mi][3]),
                          "r"(b[ni][0]), "r"(b[ni][1]));
        }
        __syncthreads();
    }
    #pragma unroll
    for (int mi = 0; mi < 2; mi++) {
        int r0 = row0 + wm * 32 + mi * 16 + gid;
        int r1 = r0 + 8;
        int cA0 = 0, cA1 = 0;
        if (EPI) {
            if (r0 < M) cA0 = ccA[r0];
            if (r1 < M) cA1 = ccA[r1];
        }
        #pragma unroll
        for (int ni = 0; ni < 8; ni++) {
            int c = wn * 64 + ni * 8 + tig * 2;
            if (EPI) {
                float cv0 = cvec[c], cv1 = cvec[c + 1];
                float b0 = bu[c], b1 = bu[c + 1];
                if (r0 < M) {
                    float u0 = lrelu(acc[mi][ni][0] + cv0 + pr[cA0 * 128 + c]     + b0);
                    float u1 = lrelu(acc[mi][ni][1] + cv1 + pr[cA0 * 128 + c + 1] + b1);
                    float2 xr = *(const float2*)(Xres + (size_t)r0 * 128 + c);
                    *(float2*)(C + (size_t)r0 * 128 + c) = make_float2(xr.x + u0, xr.y + u1);
                }
                if (r1 < M) {
                    float u2 = lrelu(acc[mi][ni][2] + cv0 + pr[cA1 * 128 + c]     + b0);
                    float u3 = lrelu(acc[mi][ni][3] + cv1 + pr[cA1 * 128 + c + 1] + b1);
                    float2 xr = *(const float2*)(Xres + (size_t)r1 * 128 + c);
                    *(float2*)(C + (size_t)r1 * 128 + c) = make_float2(xr.x + u2, xr.y + u3);
                }
            } else {
                float b0 = bias[c], b1 = bias[c + 1];
                if (r0 < M)
                    *(float2*)(C + (size_t)r0 * 128 + c) =
                        make_float2(acc[mi][ni][0] + b0, acc[mi][ni][1] + b1);
                if (r1 < M)
                    *(float2*)(C + (size_t)r1 * 128 + c) =
                        make_float2(acc[mi][ni][2] + b0, acc[mi][ni][3] + b1);
            }
        }
    }
}

// ---------------- neighbor-mean gather (warp per node) ----------------
__global__ void k_gather(const float* __restrict__ x, const int* __restrict__ rowptr,
                         const int* __restrict__ csr, float* __restrict__ xm, int n) {
    int w = (blockIdx.x * blockDim.x + threadIdx.x) >> 5;
    int lane = threadIdx.x & 31;
    if (w >= n) return;
    int beg = rowptr[w], end = rowptr[w + 1];
    float4 s  = make_float4(0.f, 0.f, 0.f, 0.f);
    float4 s2 = make_float4(0.f, 0.f, 0.f, 0.f);
    for (int base = beg; base < end; base += 32) {
        int m = min(32, end - base);
        int sv = (lane < m) ? __ldg(&csr[base + lane]) : 0;
        int j = 0;
        for (; j + 2 <= m; j += 2) {
            int sa = __shfl_sync(0xffffffffu, sv, j);
            int sb = __shfl_sync(0xffffffffu, sv, j + 1);
            float4 va = __ldg((const float4*)(x + (size_t)sa * 128 + lane * 4));
            float4 vb = __ldg((const float4*)(x + (size_t)sb * 128 + lane * 4));
            s.x += va.x; s.y += va.y; s.z += va.z; s.w += va.w;
            s2.x += vb.x; s2.y += vb.y; s2.z += vb.z; s2.w += vb.w;
        }
        if (j < m) {
            int sa = __shfl_sync(0xffffffffu, sv, j);
            float4 v = __ldg((const float4*)(x + (size_t)sa * 128 + lane * 4));
            s.x += v.x; s.y += v.y; s.z += v.z; s.w += v.w;
        }
    }
    int deg = end - beg;
    float inv = (deg > 0) ? 1.0f / (float)deg : 0.f;
    float4 o = make_float4((s.x + s2.x) * inv, (s.y + s2.y) * inv,
                           (s.z + s2.z) * inv, (s.w + s2.w) * inv);
    *(float4*)(xm + (size_t)w * 128 + lane * 4) = o;
}

// ---------------- cluster pooling + pr GEMV fused (block per cluster) ----------------
__global__ void k_poolpr(const float* __restrict__ x, const int* __restrict__ coff,
                         const int* __restrict__ cnodes, const float* __restrict__ tr,
                         const float* __restrict__ W_u, float* __restrict__ pr) {
    int c = blockIdx.x;
    int t = threadIdx.x;            // 256
    int col = t & 127, sub = t >> 7;
    int beg = coff[c], end = coff[c + 1];
    float acc = 0.f;
    for (int i = beg + sub; i < end; i += 2) {
        int nd = __ldg(&cnodes[i]);
        acc += __ldg(&x[(size_t)nd * 128 + col]);
    }
    __shared__ float red[256];
    __shared__ float prow[128];
    red[t] = acc; __syncthreads();
    if (t < 128) {
        int cnt = end - beg;
        float scale = tr[c] / (float)(cnt > 1 ? cnt : 1);
        prow[t] = (red[t] + red[t + 128]) * scale;
    }
    __syncthreads();
    if (t < 128) {
        float a = 0.f;
        #pragma unroll 8
        for (int k = 0; k < 128; k++) a += prow[k] * W_u[(256 + k) * 128 + t];
        pr[c * 128 + t] = a;
    }
}

// ---------------- deg==0 exact patch (warp per listed node) ----------------
__global__ void k_patch(const float* __restrict__ xin, const float* __restrict__ Wc,
                        const float* __restrict__ A, const float* __restrict__ pr,
                        const int* __restrict__ ccA, const float* __restrict__ bu,
                        float* __restrict__ xout, const int* __restrict__ dzlist,
                        const int* __restrict__ dzcnt) {
    int wi = (blockIdx.x * blockDim.x + threadIdx.x) >> 5;
    int lane = threadIdx.x & 31;
    int nwarps = (gridDim.x * blockDim.x) >> 5;
    int cnt = *dzcnt;
    for (int idx = wi; idx < cnt; idx += nwarps) {
        int nd = dzlist[idx];
        const float* xr = xin + (size_t)nd * 128;
        float4 t = make_float4(0.f, 0.f, 0.f, 0.f);
        for (int k = 0; k < 128; k++) {
            float xv = xr[k];
            float4 wv = __ldg((const float4*)(Wc + k * 128 + lane * 4));
            float4 av = __ldg((const float4*)(A  + k * 128 + lane * 4));
            t.x += xv * (wv.x - av.x); t.y += xv * (wv.y - av.y);
            t.z += xv * (wv.z - av.z); t.w += xv * (wv.w - av.w);
        }
        int c = ccA[nd];
        float4 p  = __ldg((const float4*)(pr + c * 128 + lane * 4));
        float4 b  = *(const float4*)(bu + lane * 4);
        float4 xi = *(const float4*)(xr + lane * 4);
        float u0 = lrelu(t.x + p.x + b.x);
        float u1 = lrelu(t.y + p.y + b.y);
        float u2 = lrelu(t.z + p.z + b.z);
        float u3 = lrelu(t.w + p.w + b.w);
        *(float4*)(xout + (size_t)nd * 128 + lane * 4) =
            make_float4(xi.x + u0, xi.y + u1, xi.z + u2, xi.w + u3);
    }
}

// ---------------- launch ----------------
extern "C" void kernel_launch(void* const* d_in, const int* in_sizes, int n_in,
                              void* d_out, int out_size) {
    const float* cf    = (const float*)d_in[0];
    const float* slf   = (const float*)d_in[1];
    const float* z     = (const float*)d_in[2];
    const float* tr    = (const float*)d_in[3];
    const float* W_enc = (const float*)d_in[4];
    const float* b_enc = (const float*)d_in[5];
    const float* W_m   = (const float*)d_in[6];
    const float* b_m   = (const float*)d_in[7];
    const float* W_u   = (const float*)d_in[8];
    const float* b_u   = (const float*)d_in[9];
    const void*  e     = d_in[10];
    const void*  cc    = d_in[11];
    float* out = (float*)d_out;

    int n  = in_sizes[0] / 15;   // 100000
    int E  = in_sizes[10] / 2;   // 600000
    int bc = in_sizes[3];        // 384

    float *x, *x2, *xm, *xin, *Wcomb, *A, *cvec, *Wenc, *pr;
    int *rowptr, *rowfill, *deg, *csr, *ccount, *coff, *cfill, *cnodes, *bsum, *bsumex;
    int *srcA, *dstA, *ccA, *flag, *dzlist, *dzcnt;
    cudaGetSymbolAddress((void**)&x,      g_x);
    cudaGetSymbolAddress((void**)&x2,     g_x2);
    cudaGetSymbolAddress((void**)&xm,     g_xm);
    cudaGetSymbolAddress((void**)&xin,    g_xin);
    cudaGetSymbolAddress((void**)&Wcomb,  g_Wcomb);
    cudaGetSymbolAddress((void**)&A,      g_A);
    cudaGetSymbolAddress((void**)&cvec,   g_cvec);
    cudaGetSymbolAddress((void**)&Wenc,   g_Wenc);
    cudaGetSymbolAddress((void**)&pr,     g_pr);
    cudaGetSymbolAddress((void**)&rowptr, g_rowptr);
    cudaGetSymbolAddress((void**)&rowfill,g_rowfill);
    cudaGetSymbolAddress((void**)&deg,    g_deg);
    cudaGetSymbolAddress((void**)&csr,    g_csr);
    cudaGetSymbolAddress((void**)&ccount, g_ccount);
    cudaGetSymbolAddress((void**)&coff,   g_coff);
    cudaGetSymbolAddress((void**)&cfill,  g_cfill);
    cudaGetSymbolAddress((void**)&cnodes, g_cnodes);
    cudaGetSymbolAddress((void**)&bsum,   g_bsum);
    cudaGetSymbolAddress((void**)&bsumex, g_bsumex);
    cudaGetSymbolAddress((void**)&srcA,   g_srcA);
    cudaGetSymbolAddress((void**)&dstA,   g_dstA);
    cudaGetSymbolAddress((void**)&ccA,    g_ccA);
    cudaGetSymbolAddress((void**)&flag,   g_flag);
    cudaGetSymbolAddress((void**)&dzlist, g_dzlist);
    cudaGetSymbolAddress((void**)&dzcnt,  g_dzcnt);

    // ---- dtype detect + CSR build ----
    k_detect<<<1, 32>>>((const int*)e, (const int*)cc, flag);
    k_zero<<<(n + 255) / 256, 256>>>(deg, ccount, dzcnt, n, bc);
    k_convhist<<<(E + 255) / 256, 256>>>(e, cc, srcA, dstA, ccA, flag, deg, ccount, E, n);
    int nb = (n + 4095) / 4096;
    k_scan_blocks<<<nb, 1024>>>(deg, rowptr, bsum, n);
    k_scan_small<<<1, 1024>>>(bsum, bsumex, nullptr, nb, 0);
    k_addoff<<<(n + 1023) / 1024, 1024>>>(rowptr, rowfill, bsumex, n, E);
    k_scan_small<<<1, 1024>>>(ccount, coff, cfill, bc, 1);
    k_scatter<<<(E + 255) / 256, 256>>>(srcA, dstA, ccA, rowfill, csr, cfill, cnodes, E, n);
    k_dzlist<<<(n + 255) / 256, 256>>>(rowptr, dzlist, dzcnt, n);

    // ---- weight folds ----
    k_fold<<<128, 256>>>(W_m, W_u, Wcomb, A);
    k_cvec<<<1, 128>>>(b_m, W_u, cvec);
    k_wenc<<<64, 128>>>(W_enc, Wenc);

    // ---- encoder ----
    k_pack<<<((size_t)n * 64 + 255) / 256, 256>>>(cf, slf, z, xin, n);
    int bm = (n + 127) / 128;
    k_gemm<64, false><<<bm, 256>>>(xin, nullptr, Wenc, b_enc,
                                   nullptr, nullptr, nullptr, nullptr, nullptr, x, n);

    // ---- 3 GNN layers (ping-pong x -> x2 -> x -> out) ----
    float* bufs_in [3] = { x,  x2, x  };
    float* bufs_out[3] = { x2, x,  out };
    int gblocks = ((size_t)n * 32 + 255) / 256;
    for (int l = 0; l < 3; l++) {
        float* xi = bufs_in[l];
        float* xo = bufs_out[l];
        k_gather<<<gblocks, 256>>>(xi, rowptr, csr, xm, n);
        k_poolpr<<<bc, 256>>>(xi, coff, cnodes, tr, W_u, pr);
        k_gemm<256, true><<<bm, 256>>>(xi, xm, Wcomb, nullptr,
                                       xi, pr, ccA, cvec, b_u, xo, n);
        k_patch<<<64, 256>>>(xi, Wcomb, A, pr, ccA, b_u, xo, dzlist, dzcnt);
    }
}

// round 10
// speedup vs baseline: 1.3420x; 1.3420x over previous
#include <cuda_runtime.h>
#include <cuda_fp16.h>
#include <cstdint>

#define NMAX   100000
#define EMAX   600000
#define HDIM   128
#define BCMAX  384

// ---------------- static scratch (no allocations allowed) ----------------
__device__ float  g_x    [NMAX * HDIM];     // node features
__device__ float  g_Y1   [NMAX * HDIM];     // x @ (Wu1 + A)   (fp32)
__device__ __half g_Y2h  [NMAX * HDIM];     // x @ B           (fp16, gathered)
__device__ float  g_xin  [NMAX * 64];       // packed encoder input (padded 48->64)
__device__ float  g_Wcomb[128 * 256];       // [Wu1+A | B], row-major 128x256
__device__ float  g_A    [128 * 128];       // Wm_i @ Wu2 (deg==0 fixup)
__device__ float  g_cvec [128];             // b_m @ Wu2
__device__ float  g_Wenc [64 * 128];        // padded encoder weight
__device__ float  g_pr   [BCMAX * HDIM];    // pooled_scaled @ Wu3
__device__ int    g_rowptr[NMAX + 1];
__device__ int    g_rowfill[NMAX];
__device__ int    g_deg  [NMAX];
__device__ int    g_csr  [EMAX];
__device__ int    g_ccount[BCMAX];
__device__ int    g_coff [BCMAX + 1];
__device__ int    g_cfill[BCMAX];
__device__ int    g_cnodes[NMAX];
__device__ int    g_bsum [64];
__device__ int    g_bsumex[64];
__device__ int    g_srcA [EMAX];
__device__ int    g_dstA [EMAX];
__device__ int    g_ccA  [NMAX];
__device__ int    g_flag [2];

// ---------------- dtype detection ----------------
// int64 little-endian values in [0, N) have every odd int32 word == 0.
__global__ void k_detect(const int* __restrict__ e32, const int* __restrict__ c32,
                         int* flag) {
    int t = threadIdx.x;  // 32 threads
    int ok_e = 1, ok_c = 1;
    for (int i = t; i < 256; i += 32) {
        ok_e &= (e32[2 * i + 1] == 0);
        ok_c &= (c32[2 * i + 1] == 0);
    }
    ok_e = __all_sync(0xffffffffu, ok_e);
    ok_c = __all_sync(0xffffffffu, ok_c);
    if (t == 0) { flag[0] = ok_e; flag[1] = ok_c; }
}

__global__ void k_zero(int* deg, int* ccount, int n, int bc) {
    int i = blockIdx.x * blockDim.x + threadIdx.x;
    if (i < n)  deg[i] = 0;
    if (i < bc) ccount[i] = 0;
}

// convert indices to int32 AND histogram in one pass
__global__ void k_convhist(const void* __restrict__ e, const void* __restrict__ cc,
                           int* __restrict__ srcA, int* __restrict__ dstA,
                           int* __restrict__ ccA, const int* __restrict__ flag,
                           int* deg, int* ccount, int E, int n) {
    int i = blockIdx.x * blockDim.x + threadIdx.x;
    int f0 = flag[0], f1 = flag[1];
    if (i < E) {
        int s, d;
        if (f0) {
            const long long* e64 = (const long long*)e;
            s = (int)e64[i]; d = (int)e64[(size_t)E + i];
        } else {
            const int* e32 = (const int*)e;
            s = e32[i]; d = e32[E + i];
        }
        if ((unsigned)s >= (unsigned)n) s = 0;
        if ((unsigned)d >= (unsigned)n) d = 0;
        srcA[i] = s; dstA[i] = d;
        atomicAdd(&deg[d], 1);
    }
    if (i < n) {
        int c = f1 ? (int)((const long long*)cc)[i] : ((const int*)cc)[i];
        if ((unsigned)c >= (unsigned)BCMAX) c = 0;
        ccA[i] = c;
        atomicAdd(&ccount[c], 1);
    }
}

// exclusive scan, 2-level: per-block (4096 elems) scan + block sums
__global__ void k_scan_blocks(const int* __restrict__ in, int* __restrict__ out,
                              int* __restrict__ bsum, int n) {
    __shared__ int sm[1024];
    int t = threadIdx.x;
    int base = blockIdx.x * 4096 + t * 4;
    int v0 = (base + 0 < n) ? in[base + 0] : 0;
    int v1 = (base + 1 < n) ? in[base + 1] : 0;
    int v2 = (base + 2 < n) ? in[base + 2] : 0;
    int v3 = (base + 3 < n) ? in[base + 3] : 0;
    int tot = v0 + v1 + v2 + v3;
    sm[t] = tot; __syncthreads();
    for (int off = 1; off < 1024; off <<= 1) {
        int add = (t >= off) ? sm[t - off] : 0;
        __syncthreads();
        sm[t] += add;
        __syncthreads();
    }
    if (t == 1023) bsum[blockIdx.x] = sm[1023];
    int run = sm[t] - tot;
    if (base + 0 < n) out[base + 0] = run; run += v0;
    if (base + 1 < n) out[base + 1] = run; run += v1;
    if (base + 2 < n) out[base + 2] = run; run += v2;
    if (base + 3 < n) out[base + 3] = run;
}

__global__ void k_scan_small(const int* __restrict__ in, int* __restrict__ out,
                             int* __restrict__ fill, int n, int writeTotal) {
    __shared__ int sm[1024];
    int t = threadIdx.x;
    int v = (t < n) ? in[t] : 0;
    sm[t] = v; __syncthreads();
    for (int off = 1; off < 1024; off <<= 1) {
        int add = (t >= off) ? sm[t - off] : 0;
        __syncthreads();
        sm[t] += add;
        __syncthreads();
    }
    if (t < n) {
        int ex = sm[t] - v;
        out[t] = ex;
        if (fill) fill[t] = ex;
    }
    if (writeTotal && t == 1023) out[n] = sm[1023];
}

// add block offsets AND seed rowfill
__global__ void k_addoff(int* rowptr, int* rowfill, const int* bsumex, int n, int total) {
    int i = blockIdx.x * blockDim.x + threadIdx.x;
    if (i < n) {
        int v = rowptr[i] + bsumex[i >> 12];
        rowptr[i] = v;
        rowfill[i] = v;
    }
    if (i == 0) rowptr[n] = total;
}

__global__ void k_scatter(const int* __restrict__ srcA, const int* __restrict__ dstA,
                          const int* __restrict__ ccA,
                          int* rowfill, int* csr, int* cfill, int* cnodes, int E, int n) {
    int i = blockIdx.x * blockDim.x + threadIdx.x;
    if (i < E) {
        int pos = atomicAdd(&rowfill[dstA[i]], 1);
        if ((unsigned)pos < (unsigned)EMAX) csr[pos] = srcA[i];
    }
    if (i < n) {
        int pos = atomicAdd(&cfill[ccA[i]], 1);
        if ((unsigned)pos < (unsigned)NMAX) cnodes[pos] = i;
    }
}

// ---------------- weight folding ----------------
// Wcomb[k][0:128]  = Wu1[k][:] + (Wm_i @ Wu2)[k][:]
// Wcomb[k][128:256]= (Wm_j @ Wu2)[k][:]
__global__ void k_fold(const float* __restrict__ W_m, const float* __restrict__ W_u,
                       float* __restrict__ Wcomb, float* __restrict__ A) {
    int k = blockIdx.x;      // 0..127
    int t = threadIdx.x;     // 0..255
    __shared__ float wi[128], wj[128];
    if (t < 128) {
        wi[t] = W_m[k * 128 + t];
        wj[t] = W_m[(128 + k) * 128 + t];
    }
    __syncthreads();
    if (t < 128) {
        float acc = 0.f;
        #pragma unroll 8
        for (int q = 0; q < 128; q++) acc += wi[q] * W_u[(128 + q) * 128 + t];
        A[k * 128 + t] = acc;
        Wcomb[k * 256 + t] = W_u[k * 128 + t] + acc;
    } else {
        int j = t - 128;
        float acc = 0.f;
        #pragma unroll 8
        for (int q = 0; q < 128; q++) acc += wj[q] * W_u[(128 + q) * 128 + j];
        Wcomb[k * 256 + 128 + j] = acc;
    }
}

__global__ void k_cvec(const float* __restrict__ b_m, const float* __restrict__ W_u,
                       float* __restrict__ cvec) {
    int j = threadIdx.x;
    float acc = 0.f;
    #pragma unroll 8
    for (int k = 0; k < 128; k++) acc += b_m[k] * W_u[(128 + k) * 128 + j];
    cvec[j] = acc;
}

__global__ void k_wenc(const float* __restrict__ W_enc, float* __restrict__ Wenc) {
    int k = blockIdx.x, h = threadIdx.x;
    Wenc[k * 128 + h] = (k < 48) ? W_enc[k * 128 + h] : 0.f;
}

__global__ void k_pack(const float* __restrict__ cf, const float* __restrict__ slf,
                       const float* __restrict__ z, float* __restrict__ xin, int n) {
    int i = blockIdx.x * blockDim.x + threadIdx.x;
    if (i >= n * 64) return;
    int nd = i >> 6, c = i & 63;
    float v;
    if (c < 15)       v = cf[nd * 15 + c];
    else if (c == 15) v = slf[nd];
    else if (c < 48)  v = z[nd * 32 + (c - 16)];
    else              v = 0.f;
    xin[i] = v;
}

// ---------------- tf32 GEMM ----------------
__device__ __forceinline__ float to_tf32(float x) {
    float r; asm("cvt.rna.tf32.f32 %0, %1;" : "=f"(r) : "f"(x)); return r;
}

// MODE 0: C[M,NC] = X@W + bias  (fp32 out)
// MODE 1 (NC=256): col block 0 -> Y1 fp32 [M,128]; col block 1 -> Yh fp16 [M,128]
template<int K, int NC, int MODE>
__global__ __launch_bounds__(256) void k_gemm(
    const float* __restrict__ X, const float* __restrict__ W,
    const float* __restrict__ bias, float* __restrict__ C,
    __half* __restrict__ Yh, int M) {
    __shared__ float As[128 * 36];
    __shared__ float Bs[32 * 132];
    const int tid = threadIdx.x;
    const int lane = tid & 31, wid = tid >> 5;
    const int wm = wid & 3, wn = wid >> 2;
    const int gid = lane >> 2, tig = lane & 3;
    const int row0 = blockIdx.x * 128;
    const int col0 = blockIdx.y * 128;
    float acc[2][8][4];
    #pragma unroll
    for (int mi = 0; mi < 2; mi++)
        #pragma unroll
        for (int ni = 0; ni < 8; ni++)
            #pragma unroll
            for (int q = 0; q < 4; q++) acc[mi][ni][q] = 0.f;

    for (int kb = 0; kb < K; kb += 32) {
        #pragma unroll
        for (int i = 0; i < 4; i++) {
            int f = tid + i * 256;
            int r = f >> 3, c4 = (f & 7) * 4;
            int grow = row0 + r;
            float4 v = make_float4(0.f, 0.f, 0.f, 0.f);
            if (grow < M) v = *(const float4*)(X + (size_t)grow * K + kb + c4);
            float* dst = &As[r * 36 + c4];
            dst[0] = to_tf32(v.x); dst[1] = to_tf32(v.y);
            dst[2] = to_tf32(v.z); dst[3] = to_tf32(v.w);
        }
        #pragma unroll
        for (int i = 0; i < 4; i++) {
            int f = tid + i * 256;
            int k = f >> 5, n4 = (f & 31) * 4;
            float4 v = *(const float4*)(W + (size_t)(kb + k) * NC + col0 + n4);
            float* dst = &Bs[k * 132 + n4];
            dst[0] = to_tf32(v.x); dst[1] = to_tf32(v.y);
            dst[2] = to_tf32(v.z); dst[3] = to_tf32(v.w);
        }
        __syncthreads();
        #pragma unroll
        for (int kk = 0; kk < 4; kk++) {
            const int kc = kk * 8;
            unsigned a[2][4];
            #pragma unroll
            for (int mi = 0; mi < 2; mi++) {
                int rb = wm * 32 + mi * 16;
                a[mi][0] = __float_as_uint(As[(rb + gid    ) * 36 + kc + tig]);
                a[mi][1] = __float_as_uint(As[(rb + gid + 8) * 36 + kc + tig]);
                a[mi][2] = __float_as_uint(As[(rb + gid    ) * 36 + kc + tig + 4]);
                a[mi][3] = __float_as_uint(As[(rb + gid + 8) * 36 + kc + tig + 4]);
            }
            unsigned b[8][2];
            #pragma unroll
            for (int ni = 0; ni < 8; ni++) {
                int cb = wn * 64 + ni * 8 + gid;
                b[ni][0] = __float_as_uint(Bs[(kc + tig    ) * 132 + cb]);
                b[ni][1] = __float_as_uint(Bs[(kc + tig + 4) * 132 + cb]);
            }
            #pragma unroll
            for (int mi = 0; mi < 2; mi++)
                #pragma unroll
                for (int ni = 0; ni < 8; ni++)
                    asm volatile(
                        "mma.sync.aligned.m16n8k8.row.col.f32.tf32.tf32.f32 "
                        "{%0,%1,%2,%3}, {%4,%5,%6,%7}, {%8,%9}, {%0,%1,%2,%3};\n"
                        : "+f"(acc[mi][ni][0]), "+f"(acc[mi][ni][1]),
                          "+f"(acc[mi][ni][2]), "+f"(acc[mi][ni][3])
                        : "r"(a[mi][0]), "r"(a[mi][1]), "r"(a[mi][2]), "r"(a[mi][3]),
                          "r"(b[ni][0]), "r"(b[ni][1]));
        }
        __syncthreads();
    }
    #pragma unroll
    for (int mi = 0; mi < 2; mi++) {
        int r0 = row0 + wm * 32 + mi * 16 + gid;
        int r1 = r0 + 8;
        #pragma unroll
        for (int ni = 0; ni < 8; ni++) {
            int lc = wn * 64 + ni * 8 + tig * 2;   // local col in [0,128)
            if (MODE == 0) {
                float b0 = bias[col0 + lc], b1 = bias[col0 + lc + 1];
                if (r0 < M)
                    *(float2*)(C + (size_t)r0 * NC + col0 + lc) =
                        make_float2(acc[mi][ni][0] + b0, acc[mi][ni][1] + b1);
                if (r1 < M)
                    *(float2*)(C + (size_t)r1 * NC + col0 + lc) =
                        make_float2(acc[mi][ni][2] + b0, acc[mi][ni][3] + b1);
            } else {
                if (blockIdx.y == 0) {
                    if (r0 < M)
                        *(float2*)(C + (size_t)r0 * 128 + lc) =
                            make_float2(acc[mi][ni][0], acc[mi][ni][1]);
                    if (r1 < M)
                        *(float2*)(C + (size_t)r1 * 128 + lc) =
                            make_float2(acc[mi][ni][2], acc[mi][ni][3]);
                } else {
                    if (r0 < M)
                        *(__half2*)(Yh + (size_t)r0 * 128 + lc) =
                            __floats2half2_rn(acc[mi][ni][0], acc[mi][ni][1]);
                    if (r1 < M)
                        *(__half2*)(Yh + (size_t)r1 * 128 + lc) =
                            __floats2half2_rn(acc[mi][ni][2], acc[mi][ni][3]);
                }
            }
        }
    }
}

// ---------------- cluster pooling + pr GEMV fused (block per cluster) ----------------
__global__ void k_poolpr(const float* __restrict__ x, const int* __restrict__ coff,
                         const int* __restrict__ cnodes, const float* __restrict__ tr,
                         const float* __restrict__ W_u, float* __restrict__ pr) {
    int c = blockIdx.x;
    int t = threadIdx.x;            // 256
    int col = t & 127, sub = t >> 7;
    int beg = coff[c], end = coff[c + 1];
    float acc = 0.f;
    for (int i = beg + sub; i < end; i += 2) {
        int nd = __ldg(&cnodes[i]);
        acc += __ldg(&x[(size_t)nd * 128 + col]);
    }
    __shared__ float red[256];
    __shared__ float prow[128];
    red[t] = acc; __syncthreads();
    if (t < 128) {
        int cnt = end - beg;
        float scale = tr[c] / (float)(cnt > 1 ? cnt : 1);
        prow[t] = (red[t] + red[t + 128]) * scale;
    }
    __syncthreads();
    if (t < 128) {
        float a = 0.f;
        #pragma unroll 8
        for (int k = 0; k < 128; k++) a += prow[k] * W_u[(256 + k) * 128 + t];
        pr[c * 128 + t] = a;
    }
}

// ---------------- fused fp16 edge aggregation + node update (warp per node) ----------------
__global__ void k_aggupd(const float* __restrict__ Y1, const __half* __restrict__ Y2,
                         const int* __restrict__ rowptr, const int* __restrict__ csr,
                         const float* __restrict__ pr, const int* __restrict__ ccA,
                         const float* __restrict__ cvec, const float* __restrict__ b_u,
                         const float* __restrict__ A, const float* __restrict__ x_in,
                         float* __restrict__ x_out, int n) {
    int w = (blockIdx.x * blockDim.x + threadIdx.x) >> 5;
    int lane = threadIdx.x & 31;
    if (w >= n) return;
    int beg = rowptr[w], end = rowptr[w + 1];
    float4 a0 = make_float4(0.f, 0.f, 0.f, 0.f);
    float4 a1 = a0, a2 = a0, a3 = a0;
    for (int base = beg; base < end; base += 32) {
        int m = min(32, end - base);
        int sv = (lane < m) ? __ldg(&csr[base + lane]) : 0;
        int j = 0;
        for (; j + 4 <= m; j += 4) {
            int s0 = __shfl_sync(0xffffffffu, sv, j);
            int s1 = __shfl_sync(0xffffffffu, sv, j + 1);
            int s2 = __shfl_sync(0xffffffffu, sv, j + 2);
            int s3 = __shfl_sync(0xffffffffu, sv, j + 3);
            uint2 r0 = __ldg((const uint2*)(Y2 + (size_t)s0 * 128 + lane * 4));
            uint2 r1 = __ldg((const uint2*)(Y2 + (size_t)s1 * 128 + lane * 4));
            uint2 r2 = __ldg((const uint2*)(Y2 + (size_t)s2 * 128 + lane * 4));
            uint2 r3 = __ldg((const uint2*)(Y2 + (size_t)s3 * 128 + lane * 4));
            float2 p, q;
            p = __half22float2(*(__half2*)&r0.x); q = __half22float2(*(__half2*)&r0.y);
            a0.x += p.x; a0.y += p.y; a0.z += q.x; a0.w += q.y;
            p = __half22float2(*(__half2*)&r1.x); q = __half22float2(*(__half2*)&r1.y);
            a1.x += p.x; a1.y += p.y; a1.z += q.x; a1.w += q.y;
            p = __half22float2(*(__half2*)&r2.x); q = __half22float2(*(__half2*)&r2.y);
            a2.x += p.x; a2.y += p.y; a2.z += q.x; a2.w += q.y;
            p = __half22float2(*(__half2*)&r3.x); q = __half22float2(*(__half2*)&r3.y);
            a3.x += p.x; a3.y += p.y; a3.z += q.x; a3.w += q.y;
        }
        for (; j < m; j++) {
            int s0 = __shfl_sync(0xffffffffu, sv, j);
            uint2 r0 = __ldg((const uint2*)(Y2 + (size_t)s0 * 128 + lane * 4));
            float2 p = __half22float2(*(__half2*)&r0.x);
            float2 q = __half22float2(*(__half2*)&r0.y);
            a0.x += p.x; a0.y += p.y; a0.z += q.x; a0.w += q.y;
        }
    }
    float4 s = make_float4(a0.x + a1.x + a2.x + a3.x,
                           a0.y + a1.y + a2.y + a3.y,
                           a0.z + a1.z + a2.z + a3.z,
                           a0.w + a1.w + a2.w + a3.w);
    int deg = end - beg;
    if (deg > 0) {
        float4 cv = *(const float4*)(cvec + lane * 4);
        float inv = 1.0f / (float)deg;
        s.x = s.x * inv + cv.x; s.y = s.y * inv + cv.y;
        s.z = s.z * inv + cv.z; s.w = s.w * inv + cv.w;
    } else {
        // fixup: subtract x@A so that Y1 (= x@(Wu1+A)) collapses to x@Wu1
        float4 t = make_float4(0.f, 0.f, 0.f, 0.f);
        const float* xr = x_in + (size_t)w * 128;
        for (int k = 0; k < 128; k++) {
            float xv = xr[k];
            float4 av = __ldg((const float4*)(A + k * 128 + lane * 4));
            t.x += xv * av.x; t.y += xv * av.y; t.z += xv * av.z; t.w += xv * av.w;
        }
        s.x = -t.x; s.y = -t.y; s.z = -t.z; s.w = -t.w;
    }
    int c = ccA[w];
    float4 y1 = __ldg((const float4*)(Y1 + (size_t)w * 128 + lane * 4));
    float4 p  = __ldg((const float4*)(pr + c * 128 + lane * 4));
    float4 bu = *(const float4*)(b_u + lane * 4);
    float4 xi = __ldg((const float4*)(x_in + (size_t)w * 128 + lane * 4));
    float u0 = y1.x + s.x + p.x + bu.x; u0 = (u0 > 0.f) ? u0 : 0.01f * u0;
    float u1 = y1.y + s.y + p.y + bu.y; u1 = (u1 > 0.f) ? u1 : 0.01f * u1;
    float u2 = y1.z + s.z + p.z + bu.z; u2 = (u2 > 0.f) ? u2 : 0.01f * u2;
    float u3 = y1.w + s.w + p.w + bu.w; u3 = (u3 > 0.f) ? u3 : 0.01f * u3;
    float4 o = make_float4(xi.x + u0, xi.y + u1, xi.z + u2, xi.w + u3);
    *(float4*)(x_out + (size_t)w * 128 + lane * 4) = o;
}

// ---------------- launch ----------------
extern "C" void kernel_launch(void* const* d_in, const int* in_sizes, int n_in,
                              void* d_out, int out_size) {
    const float* cf    = (const float*)d_in[0];
    const float* slf   = (const float*)d_in[1];
    const float* z     = (const float*)d_in[2];
    const float* tr    = (const float*)d_in[3];
    const float* W_enc = (const float*)d_in[4];
    const float* b_enc = (const float*)d_in[5];
    const float* W_m   = (const float*)d_in[6];
    const float* b_m   = (const float*)d_in[7];
    const float* W_u   = (const float*)d_in[8];
    const float* b_u   = (const float*)d_in[9];
    const void*  e     = d_in[10];
    const void*  cc    = d_in[11];
    float* out = (float*)d_out;

    int n  = in_sizes[0] / 15;   // 100000
    int E  = in_sizes[10] / 2;   // 600000
    int bc = in_sizes[3];        // 384

    float *x, *Y1, *xin, *Wcomb, *A, *cvec, *Wenc, *pr;
    __half* Y2h;
    int *rowptr, *rowfill, *deg, *csr, *ccount, *coff, *cfill, *cnodes, *bsum, *bsumex;
    int *srcA, *dstA, *ccA, *flag;
    cudaGetSymbolAddress((void**)&x,      g_x);
    cudaGetSymbolAddress((void**)&Y1,     g_Y1);
    cudaGetSymbolAddress((void**)&Y2h,    g_Y2h);
    cudaGetSymbolAddress((void**)&xin,    g_xin);
    cudaGetSymbolAddress((void**)&Wcomb,  g_Wcomb);
    cudaGetSymbolAddress((void**)&A,      g_A);
    cudaGetSymbolAddress((void**)&cvec,   g_cvec);
    cudaGetSymbolAddress((void**)&Wenc,   g_Wenc);
    cudaGetSymbolAddress((void**)&pr,     g_pr);
    cudaGetSymbolAddress((void**)&rowptr, g_rowptr);
    cudaGetSymbolAddress((void**)&rowfill,g_rowfill);
    cudaGetSymbolAddress((void**)&deg,    g_deg);
    cudaGetSymbolAddress((void**)&csr,    g_csr);
    cudaGetSymbolAddress((void**)&ccount, g_ccount);
    cudaGetSymbolAddress((void**)&coff,   g_coff);
    cudaGetSymbolAddress((void**)&cfill,  g_cfill);
    cudaGetSymbolAddress((void**)&cnodes, g_cnodes);
    cudaGetSymbolAddress((void**)&bsum,   g_bsum);
    cudaGetSymbolAddress((void**)&bsumex, g_bsumex);
    cudaGetSymbolAddress((void**)&srcA,   g_srcA);
    cudaGetSymbolAddress((void**)&dstA,   g_dstA);
    cudaGetSymbolAddress((void**)&ccA,    g_ccA);
    cudaGetSymbolAddress((void**)&flag,   g_flag);

    // ---- dtype detect + CSR build ----
    k_detect<<<1, 32>>>((const int*)e, (const int*)cc, flag);
    k_zero<<<(n + 255) / 256, 256>>>(deg, ccount, n, bc);
    k_convhist<<<(E + 255) / 256, 256>>>(e, cc, srcA, dstA, ccA, flag, deg, ccount, E, n);
    int nb = (n + 4095) / 4096;
    k_scan_blocks<<<nb, 1024>>>(deg, rowptr, bsum, n);
    k_scan_small<<<1, 1024>>>(bsum, bsumex, nullptr, nb, 0);
    k_addoff<<<(n + 1023) / 1024, 1024>>>(rowptr, rowfill, bsumex, n, E);
    k_scan_small<<<1, 1024>>>(ccount, coff, cfill, bc, 1);
    k_scatter<<<(E + 255) / 256, 256>>>(srcA, dstA, ccA, rowfill, csr, cfill, cnodes, E, n);

    // ---- weight folds ----
    k_fold<<<128, 256>>>(W_m, W_u, Wcomb, A);
    k_cvec<<<1, 128>>>(b_m, W_u, cvec);
    k_wenc<<<64, 128>>>(W_enc, Wenc);

    // ---- encoder ----
    k_pack<<<((size_t)n * 64 + 255) / 256, 256>>>(cf, slf, z, xin, n);
    int bm = (n + 127) / 128;
    k_gemm<64, 128, 0><<<dim3(bm, 1), 256>>>(xin, Wenc, b_enc, x, nullptr, n);

    // ---- 3 GNN layers ----
    int gblocks = ((size_t)n * 32 + 255) / 256;
    for (int l = 0; l < 3; l++) {
        k_gemm<128, 256, 1><<<dim3(bm, 2), 256>>>(x, Wcomb, nullptr, Y1, Y2h, n);
        k_poolpr<<<bc, 256>>>(x, coff, cnodes, tr, W_u, pr);
        float* xo = (l == 2) ? out : x;
        k_aggupd<<<gblocks, 256>>>(Y1, Y2h, rowptr, csr, pr, ccA, cvec,
                                   b_u, A, x, xo, n);
    }
}

// round 13
// speedup vs baseline: 1.3766x; 1.0257x over previous
#include <cuda_runtime.h>
#include <cuda_fp16.h>
#include <cstdint>

#define NMAX   100000
#define EMAX   600000
#define HDIM   128
#define BCMAX  384

// ---------------- static scratch (no allocations allowed) ----------------
__device__ float  g_x    [NMAX * HDIM];     // node features
__device__ __half g_Y1h  [NMAX * HDIM];     // x @ (Wu1 + A)   (fp16)
__device__ __half g_Y2h  [NMAX * HDIM];     // x @ B           (fp16, gathered)
__device__ float  g_xin  [NMAX * 64];       // packed encoder input (padded 48->64)
__device__ float  g_Wcomb[128 * 256];       // [Wu1+A | B], row-major 128x256
__device__ float  g_A    [128 * 128];       // Wm_i @ Wu2 (deg==0 fixup)
__device__ float  g_cvec [128];             // b_m @ Wu2
__device__ float  g_Wenc [64 * 128];        // padded encoder weight
__device__ float  g_pr   [BCMAX * HDIM];    // pooled_scaled @ Wu3
__device__ int    g_rowptr[NMAX + 1];
__device__ int    g_rowfill[NMAX];
__device__ int    g_deg  [NMAX];
__device__ int    g_csr  [EMAX];
__device__ int    g_ccount[BCMAX];
__device__ int    g_coff [BCMAX + 1];
__device__ int    g_cfill[BCMAX];
__device__ int    g_cnodes[NMAX];
__device__ int    g_bsum [64];
__device__ int    g_bsumex[64];
__device__ int    g_srcA [EMAX];
__device__ int    g_dstA [EMAX];
__device__ int    g_ccA  [NMAX];
__device__ int    g_flag [2];

// ---------------- dtype detection ----------------
// int64 little-endian values in [0, N) have every odd int32 word == 0.
__global__ void k_detect(const int* __restrict__ e32, const int* __restrict__ c32,
                         int* flag) {
    int t = threadIdx.x;  // 32 threads
    int ok_e = 1, ok_c = 1;
    for (int i = t; i < 256; i += 32) {
        ok_e &= (e32[2 * i + 1] == 0);
        ok_c &= (c32[2 * i + 1] == 0);
    }
    ok_e = __all_sync(0xffffffffu, ok_e);
    ok_c = __all_sync(0xffffffffu, ok_c);
    if (t == 0) { flag[0] = ok_e; flag[1] = ok_c; }
}

__global__ void k_zero(int* deg, int* ccount, int n, int bc) {
    int i = blockIdx.x * blockDim.x + threadIdx.x;
    if (i < n)  deg[i] = 0;
    if (i < bc) ccount[i] = 0;
}

// convert indices to int32 AND histogram in one pass
__global__ void k_convhist(const void* __restrict__ e, const void* __restrict__ cc,
                           int* __restrict__ srcA, int* __restrict__ dstA,
                           int* __restrict__ ccA, const int* __restrict__ flag,
                           int* deg, int* ccount, int E, int n) {
    int i = blockIdx.x * blockDim.x + threadIdx.x;
    int f0 = flag[0], f1 = flag[1];
    if (i < E) {
        int s, d;
        if (f0) {
            const long long* e64 = (const long long*)e;
            s = (int)e64[i]; d = (int)e64[(size_t)E + i];
        } else {
            const int* e32 = (const int*)e;
            s = e32[i]; d = e32[E + i];
        }
        if ((unsigned)s >= (unsigned)n) s = 0;
        if ((unsigned)d >= (unsigned)n) d = 0;
        srcA[i] = s; dstA[i] = d;
        atomicAdd(&deg[d], 1);
    }
    if (i < n) {
        int c = f1 ? (int)((const long long*)cc)[i] : ((const int*)cc)[i];
        if ((unsigned)c >= (unsigned)BCMAX) c = 0;
        ccA[i] = c;
        atomicAdd(&ccount[c], 1);
    }
}

// exclusive scan, 2-level: per-block (4096 elems) scan + block sums
__global__ void k_scan_blocks(const int* __restrict__ in, int* __restrict__ out,
                              int* __restrict__ bsum, int n) {
    __shared__ int sm[1024];
    int t = threadIdx.x;
    int base = blockIdx.x * 4096 + t * 4;
    int v0 = (base + 0 < n) ? in[base + 0] : 0;
    int v1 = (base + 1 < n) ? in[base + 1] : 0;
    int v2 = (base + 2 < n) ? in[base + 2] : 0;
    int v3 = (base + 3 < n) ? in[base + 3] : 0;
    int tot = v0 + v1 + v2 + v3;
    sm[t] = tot; __syncthreads();
    for (int off = 1; off < 1024; off <<= 1) {
        int add = (t >= off) ? sm[t - off] : 0;
        __syncthreads();
        sm[t] += add;
        __syncthreads();
    }
    if (t == 1023) bsum[blockIdx.x] = sm[1023];
    int run = sm[t] - tot;
    if (base + 0 < n) out[base + 0] = run; run += v0;
    if (base + 1 < n) out[base + 1] = run; run += v1;
    if (base + 2 < n) out[base + 2] = run; run += v2;
    if (base + 3 < n) out[base + 3] = run;
}

__global__ void k_scan_small(const int* __restrict__ in, int* __restrict__ out,
                             int* __restrict__ fill, int n, int writeTotal) {
    __shared__ int sm[1024];
    int t = threadIdx.x;
    int v = (t < n) ? in[t] : 0;
    sm[t] = v; __syncthreads();
    for (int off = 1; off < 1024; off <<= 1) {
        int add = (t >= off) ? sm[t - off] : 0;
        __syncthreads();
        sm[t] += add;
        __syncthreads();
    }
    if (t < n) {
        int ex = sm[t] - v;
        out[t] = ex;
        if (fill) fill[t] = ex;
    }
    if (writeTotal && t == 1023) out[n] = sm[1023];
}

// add block offsets AND seed rowfill
__global__ void k_addoff(int* rowptr, int* rowfill, const int* bsumex, int n, int total) {
    int i = blockIdx.x * blockDim.x + threadIdx.x;
    if (i < n) {
        int v = rowptr[i] + bsumex[i >> 12];
        rowptr[i] = v;
        rowfill[i] = v;
    }
    if (i == 0) rowptr[n] = total;
}

__global__ void k_scatter(const int* __restrict__ srcA, const int* __restrict__ dstA,
                          const int* __restrict__ ccA,
                          int* rowfill, int* csr, int* cfill, int* cnodes, int E, int n) {
    int i = blockIdx.x * blockDim.x + threadIdx.x;
    if (i < E) {
        int pos = atomicAdd(&rowfill[dstA[i]], 1);
        if ((unsigned)pos < (unsigned)EMAX) csr[pos] = srcA[i];
    }
    if (i < n) {
        int pos = atomicAdd(&cfill[ccA[i]], 1);
        if ((unsigned)pos < (unsigned)NMAX) cnodes[pos] = i;
    }
}

// ---------------- weight folding ----------------
// Wcomb[k][0:128]  = Wu1[k][:] + (Wm_i @ Wu2)[k][:]
// Wcomb[k][128:256]= (Wm_j @ Wu2)[k][:]
__global__ void k_fold(const float* __restrict__ W_m, const float* __restrict__ W_u,
                       float* __restrict__ Wcomb, float* __restrict__ A) {
    int k = blockIdx.x;      // 0..127
    int t = threadIdx.x;     // 0..255
    __shared__ float wi[128], wj[128];
    if (t < 128) {
        wi[t] = W_m[k * 128 + t];
        wj[t] = W_m[(128 + k) * 128 + t];
    }
    __syncthreads();
    if (t < 128) {
        float acc = 0.f;
        #pragma unroll 8
        for (int q = 0; q < 128; q++) acc += wi[q] * W_u[(128 + q) * 128 + t];
        A[k * 128 + t] = acc;
        Wcomb[k * 256 + t] = W_u[k * 128 + t] + acc;
    } else {
        int j = t - 128;
        float acc = 0.f;
        #pragma unroll 8
        for (int q = 0; q < 128; q++) acc += wj[q] * W_u[(128 + q) * 128 + j];
        Wcomb[k * 256 + 128 + j] = acc;
    }
}

__global__ void k_cvec(const float* __restrict__ b_m, const float* __restrict__ W_u,
                       float* __restrict__ cvec) {
    int j = threadIdx.x;
    float acc = 0.f;
    #pragma unroll 8
    for (int k = 0; k < 128; k++) acc += b_m[k] * W_u[(128 + k) * 128 + j];
    cvec[j] = acc;
}

__global__ void k_wenc(const float* __restrict__ W_enc, float* __restrict__ Wenc) {
    int k = blockIdx.x, h = threadIdx.x;
    Wenc[k * 128 + h] = (k < 48) ? W_enc[k * 128 + h] : 0.f;
}

__global__ void k_pack(const float* __restrict__ cf, const float* __restrict__ slf,
                       const float* __restrict__ z, float* __restrict__ xin, int n) {
    int i = blockIdx.x * blockDim.x + threadIdx.x;
    if (i >= n * 64) return;
    int nd = i >> 6, c = i & 63;
    float v;
    if (c < 15)       v = cf[nd * 15 + c];
    else if (c == 15) v = slf[nd];
    else if (c < 48)  v = z[nd * 32 + (c - 16)];
    else              v = 0.f;
    xin[i] = v;
}

// ---------------- tf32 GEMM ----------------
__device__ __forceinline__ float to_tf32(float x) {
    float r; asm("cvt.rna.tf32.f32 %0, %1;" : "=f"(r) : "f"(x)); return r;
}

// MODE 0: C[M,NC] = X@W + bias  (fp32 out)
// MODE 1 (NC=256): col block 0 -> Y1h fp16 [M,128]; col block 1 -> Y2h fp16 [M,128]
template<int K, int NC, int MODE>
__global__ __launch_bounds__(256) void k_gemm(
    const float* __restrict__ X, const float* __restrict__ W,
    const float* __restrict__ bias, float* __restrict__ C,
    __half* __restrict__ Y1h, __half* __restrict__ Y2h, int M) {
    __shared__ float As[128 * 36];
    __shared__ float Bs[32 * 132];
    const int tid = threadIdx.x;
    const int lane = tid & 31, wid = tid >> 5;
    const int wm = wid & 3, wn = wid >> 2;
    const int gid = lane >> 2, tig = lane & 3;
    const int row0 = blockIdx.x * 128;
    const int col0 = blockIdx.y * 128;
    float acc[2][8][4];
    #pragma unroll
    for (int mi = 0; mi < 2; mi++)
        #pragma unroll
        for (int ni = 0; ni < 8; ni++)
            #pragma unroll
            for (int q = 0; q < 4; q++) acc[mi][ni][q] = 0.f;

    for (int kb = 0; kb < K; kb += 32) {
        #pragma unroll
        for (int i = 0; i < 4; i++) {
            int f = tid + i * 256;
            int r = f >> 3, c4 = (f & 7) * 4;
            int grow = row0 + r;
            float4 v = make_float4(0.f, 0.f, 0.f, 0.f);
            if (grow < M) v = *(const float4*)(X + (size_t)grow * K + kb + c4);
            float* dst = &As[r * 36 + c4];
            dst[0] = to_tf32(v.x); dst[1] = to_tf32(v.y);
            dst[2] = to_tf32(v.z); dst[3] = to_tf32(v.w);
        }
        #pragma unroll
        for (int i = 0; i < 4; i++) {
            int f = tid + i * 256;
            int k = f >> 5, n4 = (f & 31) * 4;
            float4 v = *(const float4*)(W + (size_t)(kb + k) * NC + col0 + n4);
            float* dst = &Bs[k * 132 + n4];
            dst[0] = to_tf32(v.x); dst[1] = to_tf32(v.y);
            dst[2] = to_tf32(v.z); dst[3] = to_tf32(v.w);
        }
        __syncthreads();
        #pragma unroll
        for (int kk = 0; kk < 4; kk++) {
            const int kc = kk * 8;
            unsigned a[2][4];
            #pragma unroll
            for (int mi = 0; mi < 2; mi++) {
                int rb = wm * 32 + mi * 16;
                a[mi][0] = __float_as_uint(As[(rb + gid    ) * 36 + kc + tig]);
                a[mi][1] = __float_as_uint(As[(rb + gid + 8) * 36 + kc + tig]);
                a[mi][2] = __float_as_uint(As[(rb + gid    ) * 36 + kc + tig + 4]);
                a[mi][3] = __float_as_uint(As[(rb + gid + 8) * 36 + kc + tig + 4]);
            }
            unsigned b[8][2];
            #pragma unroll
            for (int ni = 0; ni < 8; ni++) {
                int cb = wn * 64 + ni * 8 + gid;
                b[ni][0] = __float_as_uint(Bs[(kc + tig    ) * 132 + cb]);
                b[ni][1] = __float_as_uint(Bs[(kc + tig + 4) * 132 + cb]);
            }
            #pragma unroll
            for (int mi = 0; mi < 2; mi++)
                #pragma unroll
                for (int ni = 0; ni < 8; ni++)
                    asm volatile(
                        "mma.sync.aligned.m16n8k8.row.col.f32.tf32.tf32.f32 "
                        "{%0,%1,%2,%3}, {%4,%5,%6,%7}, {%8,%9}, {%0,%1,%2,%3};\n"
                        : "+f"(acc[mi][ni][0]), "+f"(acc[mi][ni][1]),
                          "+f"(acc[mi][ni][2]), "+f"(acc[mi][ni][3])
                        : "r"(a[mi][0]), "r"(a[mi][1]), "r"(a[mi][2]), "r"(a[mi][3]),
                          "r"(b[ni][0]), "r"(b[ni][1]));
        }
        __syncthreads();
    }
    #pragma unroll
    for (int mi = 0; mi < 2; mi++) {
        int r0 = row0 + wm * 32 + mi * 16 + gid;
        int r1 = r0 + 8;
        #pragma unroll
        for (int ni = 0; ni < 8; ni++) {
            int lc = wn * 64 + ni * 8 + tig * 2;   // local col in [0,128)
            if (MODE == 0) {
                float b0 = bias[col0 + lc], b1 = bias[col0 + lc + 1];
                if (r0 < M)
                    *(float2*)(C + (size_t)r0 * NC + col0 + lc) =
                        make_float2(acc[mi][ni][0] + b0, acc[mi][ni][1] + b1);
                if (r1 < M)
                    *(float2*)(C + (size_t)r1 * NC + col0 + lc) =
                        make_float2(acc[mi][ni][2] + b0, acc[mi][ni][3] + b1);
            } else {
                __half* dst = (blockIdx.y == 0) ? Y1h : Y2h;
                if (r0 < M)
                    *(__half2*)(dst + (size_t)r0 * 128 + lc) =
                        __floats2half2_rn(acc[mi][ni][0], acc[mi][ni][1]);
                if (r1 < M)
                    *(__half2*)(dst + (size_t)r1 * 128 + lc) =
                        __floats2half2_rn(acc[mi][ni][2], acc[mi][ni][3]);
            }
        }
    }
}

// ---------------- cluster pooling + pr GEMV fused (block per cluster) ----------------
__global__ void k_poolpr(const float* __restrict__ x, const int* __restrict__ coff,
                         const int* __restrict__ cnodes, const float* __restrict__ tr,
                         const float* __restrict__ W_u, float* __restrict__ pr) {
    int c = blockIdx.x;
    int t = threadIdx.x;            // 256
    int col = t & 127, sub = t >> 7;
    int beg = coff[c], end = coff[c + 1];
    float acc = 0.f;
    for (int i = beg + sub; i < end; i += 2) {
        int nd = __ldg(&cnodes[i]);
        acc += __ldg(&x[(size_t)nd * 128 + col]);
    }
    __shared__ float red[256];
    __shared__ float prow[128];
    red[t] = acc; __syncthreads();
    if (t < 128) {
        int cnt = end - beg;
        float scale = tr[c] / (float)(cnt > 1 ? cnt : 1);
        prow[t] = (red[t] + red[t + 128]) * scale;
    }
    __syncthreads();
    if (t < 128) {
        float a = 0.f;
        #pragma unroll 8
        for (int k = 0; k < 128; k++) a += prow[k] * W_u[(256 + k) * 128 + t];
        pr[c * 128 + t] = a;
    }
}

// ---------------- fused fp16 edge aggregation + node update (warp per node) ----------------
__global__ void k_aggupd(const __half* __restrict__ Y1, const __half* __restrict__ Y2,
                         const int* __restrict__ rowptr, const int* __restrict__ csr,
                         const float* __restrict__ pr, const int* __restrict__ ccA,
                         const float* __restrict__ cvec, const float* __restrict__ b_u,
                         const float* __restrict__ A, const float* __restrict__ x_in,
                         float* __restrict__ x_out, int n) {
    int w = (blockIdx.x * blockDim.x + threadIdx.x) >> 5;
    int lane = threadIdx.x & 31;
    if (w >= n) return;
    int beg = rowptr[w], end = rowptr[w + 1];
    float4 a0 = make_float4(0.f, 0.f, 0.f, 0.f);
    float4 a1 = a0, a2 = a0, a3 = a0;
    for (int base = beg; base < end; base += 32) {
        int m = min(32, end - base);
        int sv = (lane < m) ? __ldg(&csr[base + lane]) : 0;
        int j = 0;
        for (; j + 4 <= m; j += 4) {
            int s0 = __shfl_sync(0xffffffffu, sv, j);
            int s1 = __shfl_sync(0xffffffffu, sv, j + 1);
            int s2 = __shfl_sync(0xffffffffu, sv, j + 2);
            int s3 = __shfl_sync(0xffffffffu, sv, j + 3);
            uint2 r0 = __ldg((const uint2*)(Y2 + (size_t)s0 * 128 + lane * 4));
            uint2 r1 = __ldg((const uint2*)(Y2 + (size_t)s1 * 128 + lane * 4));
            uint2 r2 = __ldg((const uint2*)(Y2 + (size_t)s2 * 128 + lane * 4));
            uint2 r3 = __ldg((const uint2*)(Y2 + (size_t)s3 * 128 + lane * 4));
            float2 p, q;
            p = __half22float2(*(__half2*)&r0.x); q = __half22float2(*(__half2*)&r0.y);
            a0.x += p.x; a0.y += p.y; a0.z += q.x; a0.w += q.y;
            p = __half22float2(*(__half2*)&r1.x); q = __half22float2(*(__half2*)&r1.y);
            a1.x += p.x; a1.y += p.y; a1.z += q.x; a1.w += q.y;
            p = __half22float2(*(__half2*)&r2.x); q = __half22float2(*(__half2*)&r2.y);
            a2.x += p.x; a2.y += p.y; a2.z += q.x; a2.w += q.y;
            p = __half22float2(*(__half2*)&r3.x); q = __half22float2(*(__half2*)&r3.y);
            a3.x += p.x; a3.y += p.y; a3.z += q.x; a3.w += q.y;
        }
        for (; j < m; j++) {
            int s0 = __shfl_sync(0xffffffffu, sv, j);
            uint2 r0 = __ldg((const uint2*)(Y2 + (size_t)s0 * 128 + lane * 4));
            float2 p = __half22float2(*(__half2*)&r0.x);
            float2 q = __half22float2(*(__half2*)&r0.y);
            a0.x += p.x; a0.y += p.y; a0.z += q.x; a0.w += q.y;
        }
    }
    float4 s = make_float4(a0.x + a1.x + a2.x + a3.x,
                           a0.y + a1.y + a2.y + a3.y,
                           a0.z + a1.z + a2.z + a3.z,
                           a0.w + a1.w + a2.w + a3.w);
    int deg = end - beg;
    if (deg > 0) {
        float4 cv = *(const float4*)(cvec + lane * 4);
        float inv = 1.0f / (float)deg;
        s.x = s.x * inv + cv.x; s.y = s.y * inv + cv.y;
        s.z = s.z * inv + cv.z; s.w = s.w * inv + cv.w;
    } else {
        // fixup: subtract x@A so that Y1 (= x@(Wu1+A)) collapses to x@Wu1
        float4 t = make_float4(0.f, 0.f, 0.f, 0.f);
        const float* xr = x_in + (size_t)w * 128;
        for (int k = 0; k < 128; k++) {
            float xv = xr[k];
            float4 av = __ldg((const float4*)(A + k * 128 + lane * 4));
            t.x += xv * av.x; t.y += xv * av.y; t.z += xv * av.z; t.w += xv * av.w;
        }
        s.x = -t.x; s.y = -t.y; s.z = -t.z; s.w = -t.w;
    }
    int c = ccA[w];
    uint2 y1r = __ldg((const uint2*)(Y1 + (size_t)w * 128 + lane * 4));
    float2 y1a = __half22float2(*(__half2*)&y1r.x);
    float2 y1b = __half22float2(*(__half2*)&y1r.y);
    float4 p  = __ldg((const float4*)(pr + c * 128 + lane * 4));
    float4 bu = *(const float4*)(b_u + lane * 4);
    float4 xi = __ldg((const float4*)(x_in + (size_t)w * 128 + lane * 4));
    float u0 = y1a.x + s.x + p.x + bu.x; u0 = (u0 > 0.f) ? u0 : 0.01f * u0;
    float u1 = y1a.y + s.y + p.y + bu.y; u1 = (u1 > 0.f) ? u1 : 0.01f * u1;
    float u2 = y1b.x + s.z + p.z + bu.z; u2 = (u2 > 0.f) ? u2 : 0.01f * u2;
    float u3 = y1b.y + s.w + p.w + bu.w; u3 = (u3 > 0.f) ? u3 : 0.01f * u3;
    float4 o = make_float4(xi.x + u0, xi.y + u1, xi.z + u2, xi.w + u3);
    *(float4*)(x_out + (size_t)w * 128 + lane * 4) = o;
}

// ---------------- launch ----------------
extern "C" void kernel_launch(void* const* d_in, const int* in_sizes, int n_in,
                              void* d_out, int out_size) {
    const float* cf    = (const float*)d_in[0];
    const float* slf   = (const float*)d_in[1];
    const float* z     = (const float*)d_in[2];
    const float* tr    = (const float*)d_in[3];
    const float* W_enc = (const float*)d_in[4];
    const float* b_enc = (const float*)d_in[5];
    const float* W_m   = (const float*)d_in[6];
    const float* b_m   = (const float*)d_in[7];
    const float* W_u   = (const float*)d_in[8];
    const float* b_u   = (const float*)d_in[9];
    const void*  e     = d_in[10];
    const void*  cc    = d_in[11];
    float* out = (float*)d_out;

    int n  = in_sizes[0] / 15;   // 100000
    int E  = in_sizes[10] / 2;   // 600000
    int bc = in_sizes[3];        // 384

    float *x, *xin, *Wcomb, *A, *cvec, *Wenc, *pr;
    __half *Y1h, *Y2h;
    int *rowptr, *rowfill, *deg, *csr, *ccount, *coff, *cfill, *cnodes, *bsum, *bsumex;
    int *srcA, *dstA, *ccA, *flag;
    cudaGetSymbolAddress((void**)&x,      g_x);
    cudaGetSymbolAddress((void**)&Y1h,    g_Y1h);
    cudaGetSymbolAddress((void**)&Y2h,    g_Y2h);
    cudaGetSymbolAddress((void**)&xin,    g_xin);
    cudaGetSymbolAddress((void**)&Wcomb,  g_Wcomb);
    cudaGetSymbolAddress((void**)&A,      g_A);
    cudaGetSymbolAddress((void**)&cvec,   g_cvec);
    cudaGetSymbolAddress((void**)&Wenc,   g_Wenc);
    cudaGetSymbolAddress((void**)&pr,     g_pr);
    cudaGetSymbolAddress((void**)&rowptr, g_rowptr);
    cudaGetSymbolAddress((void**)&rowfill,g_rowfill);
    cudaGetSymbolAddress((void**)&deg,    g_deg);
    cudaGetSymbolAddress((void**)&csr,    g_csr);
    cudaGetSymbolAddress((void**)&ccount, g_ccount);
    cudaGetSymbolAddress((void**)&coff,   g_coff);
    cudaGetSymbolAddress((void**)&cfill,  g_cfill);
    cudaGetSymbolAddress((void**)&cnodes, g_cnodes);
    cudaGetSymbolAddress((void**)&bsum,   g_bsum);
    cudaGetSymbolAddress((void**)&bsumex, g_bsumex);
    cudaGetSymbolAddress((void**)&srcA,   g_srcA);
    cudaGetSymbolAddress((void**)&dstA,   g_dstA);
    cudaGetSymbolAddress((void**)&ccA,    g_ccA);
    cudaGetSymbolAddress((void**)&flag,   g_flag);

    int bm = (n + 127) / 128;

    // ---- encoder + folds first; layer-1 GEMM is launch #5 (profiled by ncu -s 5) ----
    k_wenc<<<64, 128>>>(W_enc, Wenc);                                           // 0
    k_pack<<<((size_t)n * 64 + 255) / 256, 256>>>(cf, slf, z, xin, n);          // 1
    k_gemm<64, 128, 0><<<dim3(bm, 1), 256>>>(xin, Wenc, b_enc, x,
                                             nullptr, nullptr, n);              // 2
    k_fold<<<128, 256>>>(W_m, W_u, Wcomb, A);                                   // 3
    k_cvec<<<1, 128>>>(b_m, W_u, cvec);                                         // 4
    k_gemm<128, 256, 1><<<dim3(bm, 2), 256>>>(x, Wcomb, nullptr, nullptr,
                                              Y1h, Y2h, n);                     // 5 <- profiled

    // ---- CSR build (needed before poolpr/aggupd) ----
    k_detect<<<1, 32>>>((const int*)e, (const int*)cc, flag);
    k_zero<<<(n + 255) / 256, 256>>>(deg, ccount, n, bc);
    k_convhist<<<(E + 255) / 256, 256>>>(e, cc, srcA, dstA, ccA, flag, deg, ccount, E, n);
    int nb = (n + 4095) / 4096;
    k_scan_blocks<<<nb, 1024>>>(deg, rowptr, bsum, n);
    k_scan_small<<<1, 1024>>>(bsum, bsumex, nullptr, nb, 0);
    k_addoff<<<(n + 1023) / 1024, 1024>>>(rowptr, rowfill, bsumex, n, E);
    k_scan_small<<<1, 1024>>>(ccount, coff, cfill, bc, 1);
    k_scatter<<<(E + 255) / 256, 256>>>(srcA, dstA, ccA, rowfill, csr, cfill, cnodes, E, n);

    // ---- 3 GNN layers (layer-1 GEMM already issued above) ----
    int gblocks = ((size_t)n * 32 + 255) / 256;
    for (int l = 0; l < 3; l++) {
        if (l > 0)
            k_gemm<128, 256, 1><<<dim3(bm, 2), 256>>>(x, Wcomb, nullptr, nullptr,
                                                      Y1h, Y2h, n);
        k_poolpr<<<bc, 256>>>(x, coff, cnodes, tr, W_u, pr);
        float* xo = (l == 2) ? out : x;
        k_aggupd<<<gblocks, 256>>>(Y1h, Y2h, rowptr, csr, pr, ccA, cvec,
                                   b_u, A, x, xo, n);
    }
}

// round 14
// speedup vs baseline: 1.6017x; 1.1635x over previous
#include <cuda_runtime.h>
#include <cuda_fp16.h>
#include <cstdint>

#define NMAX   100000
#define EMAX   600000
#define HDIM   128
#define BCMAX  384

// ---------------- static scratch (no allocations allowed) ----------------
__device__ float  g_x    [NMAX * HDIM];     // node features fp32 (residual-exact)
__device__ __half g_xh   [NMAX * HDIM];     // node features fp16 (GEMM A / pool)
__device__ __half g_Y1h  [NMAX * HDIM];     // x @ (Wu1 + A)   (fp16)
__device__ __half g_Y2h  [NMAX * HDIM];     // x @ B           (fp16, gathered)
__device__ __half g_xinh [NMAX * 64];       // packed encoder input fp16 (48->64 pad)
__device__ __half g_WcombT[256 * 128];      // transposed [n][k]: n<128 Wu1+A ; n>=128 B
__device__ __half g_WencT [128 * 64];       // transposed padded encoder weight [n][k]
__device__ float  g_A    [128 * 128];       // Wm_i @ Wu2 fp32 (deg==0 fixup)
__device__ float  g_cvec [128];             // b_m @ Wu2
__device__ float  g_pr   [BCMAX * HDIM];    // pooled_scaled @ Wu3
__device__ int    g_rowptr[NMAX + 1];
__device__ int    g_rowfill[NMAX];
__device__ int    g_deg  [NMAX];
__device__ int    g_csr  [EMAX];
__device__ int    g_ccount[BCMAX];
__device__ int    g_coff [BCMAX + 1];
__device__ int    g_cfill[BCMAX];
__device__ int    g_cnodes[NMAX];
__device__ int    g_bsum [64];
__device__ int    g_bsumex[64];
__device__ int    g_srcA [EMAX];
__device__ int    g_dstA [EMAX];
__device__ int    g_ccA  [NMAX];
__device__ int    g_flag [2];

// ---------------- dtype detection ----------------
__global__ void k_detect(const int* __restrict__ e32, const int* __restrict__ c32,
                         int* flag) {
    int t = threadIdx.x;
    int ok_e = 1, ok_c = 1;
    for (int i = t; i < 256; i += 32) {
        ok_e &= (e32[2 * i + 1] == 0);
        ok_c &= (c32[2 * i + 1] == 0);
    }
    ok_e = __all_sync(0xffffffffu, ok_e);
    ok_c = __all_sync(0xffffffffu, ok_c);
    if (t == 0) { flag[0] = ok_e; flag[1] = ok_c; }
}

__global__ void k_zero(int* deg, int* ccount, int n, int bc) {
    int i = blockIdx.x * blockDim.x + threadIdx.x;
    if (i < n)  deg[i] = 0;
    if (i < bc) ccount[i] = 0;
}

__global__ void k_convhist(const void* __restrict__ e, const void* __restrict__ cc,
                           int* __restrict__ srcA, int* __restrict__ dstA,
                           int* __restrict__ ccA, const int* __restrict__ flag,
                           int* deg, int* ccount, int E, int n) {
    int i = blockIdx.x * blockDim.x + threadIdx.x;
    int f0 = flag[0], f1 = flag[1];
    if (i < E) {
        int s, d;
        if (f0) {
            const long long* e64 = (const long long*)e;
            s = (int)e64[i]; d = (int)e64[(size_t)E + i];
        } else {
            const int* e32 = (const int*)e;
            s = e32[i]; d = e32[E + i];
        }
        if ((unsigned)s >= (unsigned)n) s = 0;
        if ((unsigned)d >= (unsigned)n) d = 0;
        srcA[i] = s; dstA[i] = d;
        atomicAdd(&deg[d], 1);
    }
    if (i < n) {
        int c = f1 ? (int)((const long long*)cc)[i] : ((const int*)cc)[i];
        if ((unsigned)c >= (unsigned)BCMAX) c = 0;
        ccA[i] = c;
        atomicAdd(&ccount[c], 1);
    }
}

__global__ void k_scan_blocks(const int* __restrict__ in, int* __restrict__ out,
                              int* __restrict__ bsum, int n) {
    __shared__ int sm[1024];
    int t = threadIdx.x;
    int base = blockIdx.x * 4096 + t * 4;
    int v0 = (base + 0 < n) ? in[base + 0] : 0;
    int v1 = (base + 1 < n) ? in[base + 1] : 0;
    int v2 = (base + 2 < n) ? in[base + 2] : 0;
    int v3 = (base + 3 < n) ? in[base + 3] : 0;
    int tot = v0 + v1 + v2 + v3;
    sm[t] = tot; __syncthreads();
    for (int off = 1; off < 1024; off <<= 1) {
        int add = (t >= off) ? sm[t - off] : 0;
        __syncthreads();
        sm[t] += add;
        __syncthreads();
    }
    if (t == 1023) bsum[blockIdx.x] = sm[1023];
    int run = sm[t] - tot;
    if (base + 0 < n) out[base + 0] = run; run += v0;
    if (base + 1 < n) out[base + 1] = run; run += v1;
    if (base + 2 < n) out[base + 2] = run; run += v2;
    if (base + 3 < n) out[base + 3] = run;
}

__global__ void k_scan_small(const int* __restrict__ in, int* __restrict__ out,
                             int* __restrict__ fill, int n, int writeTotal) {
    __shared__ int sm[1024];
    int t = threadIdx.x;
    int v = (t < n) ? in[t] : 0;
    sm[t] = v; __syncthreads();
    for (int off = 1; off < 1024; off <<= 1) {
        int add = (t >= off) ? sm[t - off] : 0;
        __syncthreads();
        sm[t] += add;
        __syncthreads();
    }
    if (t < n) {
        int ex = sm[t] - v;
        out[t] = ex;
        if (fill) fill[t] = ex;
    }
    if (writeTotal && t == 1023) out[n] = sm[1023];
}

__global__ void k_addoff(int* rowptr, int* rowfill, const int* bsumex, int n, int total) {
    int i = blockIdx.x * blockDim.x + threadIdx.x;
    if (i < n) {
        int v = rowptr[i] + bsumex[i >> 12];
        rowptr[i] = v;
        rowfill[i] = v;
    }
    if (i == 0) rowptr[n] = total;
}

__global__ void k_scatter(const int* __restrict__ srcA, const int* __restrict__ dstA,
                          const int* __restrict__ ccA,
                          int* rowfill, int* csr, int* cfill, int* cnodes, int E, int n) {
    int i = blockIdx.x * blockDim.x + threadIdx.x;
    if (i < E) {
        int pos = atomicAdd(&rowfill[dstA[i]], 1);
        if ((unsigned)pos < (unsigned)EMAX) csr[pos] = srcA[i];
    }
    if (i < n) {
        int pos = atomicAdd(&cfill[ccA[i]], 1);
        if ((unsigned)pos < (unsigned)NMAX) cnodes[pos] = i;
    }
}

// ---------------- weight folding (transposed fp16 outputs) ----------------
// WcombT[n][k] (n<128)  = Wu1[k][n] + (Wm_i @ Wu2)[k][n]
// WcombT[128+j][k]      = (Wm_j @ Wu2)[k][j]
__global__ void k_foldT(const float* __restrict__ W_m, const float* __restrict__ W_u,
                        __half* __restrict__ WcombT, float* __restrict__ A) {
    int k = blockIdx.x;      // 0..127
    int t = threadIdx.x;     // 0..255
    __shared__ float wi[128], wj[128];
    if (t < 128) {
        wi[t] = W_m[k * 128 + t];
        wj[t] = W_m[(128 + k) * 128 + t];
    }
    __syncthreads();
    if (t < 128) {
        float acc = 0.f;
        #pragma unroll 8
        for (int q = 0; q < 128; q++) acc += wi[q] * W_u[(128 + q) * 128 + t];
        A[k * 128 + t] = acc;
        WcombT[t * 128 + k] = __float2half(W_u[k * 128 + t] + acc);
    } else {
        int j = t - 128;
        float acc = 0.f;
        #pragma unroll 8
        for (int q = 0; q < 128; q++) acc += wj[q] * W_u[(128 + q) * 128 + j];
        WcombT[(128 + j) * 128 + k] = __float2half(acc);
    }
}

__global__ void k_cvec(const float* __restrict__ b_m, const float* __restrict__ W_u,
                       float* __restrict__ cvec) {
    int j = threadIdx.x;
    float acc = 0.f;
    #pragma unroll 8
    for (int k = 0; k < 128; k++) acc += b_m[k] * W_u[(128 + k) * 128 + j];
    cvec[j] = acc;
}

// WencT[n][k] = (k<48) ? W_enc[k][n] : 0   (fp16, n=0..127, k=0..63)
__global__ void k_wencT(const float* __restrict__ W_enc, __half* __restrict__ WencT) {
    int nn = blockIdx.x, k = threadIdx.x;   // 128 blocks x 64 threads
    WencT[nn * 64 + k] = __float2half((k < 48) ? W_enc[k * 128 + nn] : 0.f);
}

__global__ void k_pack(const float* __restrict__ cf, const float* __restrict__ slf,
                       const float* __restrict__ z, __half* __restrict__ xinh, int n) {
    int i = blockIdx.x * blockDim.x + threadIdx.x;
    if (i >= n * 64) return;
    int nd = i >> 6, c = i & 63;
    float v;
    if (c < 15)       v = cf[nd * 15 + c];
    else if (c == 15) v = slf[nd];
    else if (c < 48)  v = z[nd * 32 + (c - 16)];
    else              v = 0.f;
    xinh[i] = __float2half(v);
}

// ---------------- fp16 HMMA GEMM: C[M,128/256] = Xh[M,K] @ WT^T ----------------
// WT is [NC][K] n-major fp16. mma.m16n8k16 f32.f16.f16.f32.
// MODE 0 (encoder): NC=128, out = fp32 x + fp16 xh, bias added.
// MODE 1 (layer):   NC=256, blockIdx.y picks col block: 0 -> Y1h, 1 -> Y2h.
template<int K, int MODE>
__global__ __launch_bounds__(256) void k_gemmh(
    const __half* __restrict__ Xh, const __half* __restrict__ WT,
    const float* __restrict__ bias,
    float* __restrict__ Cx, __half* __restrict__ Cxh,
    __half* __restrict__ Y1h, __half* __restrict__ Y2h, int M) {
    __shared__ __half As[128 * 72];
    __shared__ __half Bs[128 * 72];
    const int tid = threadIdx.x;
    const int lane = tid & 31, wid = tid >> 5;
    const int wm = wid & 3, wn = wid >> 2;          // wm 0-3 (M), wn 0-1 (N)
    const int gid = lane >> 2, tig = lane & 3;
    const int row0 = blockIdx.x * 128;
    const int col0 = (MODE == 1) ? blockIdx.y * 128 : 0;
    float acc[2][8][4];
    #pragma unroll
    for (int mi = 0; mi < 2; mi++)
        #pragma unroll
        for (int ni = 0; ni < 8; ni++)
            #pragma unroll
            for (int q = 0; q < 4; q++) acc[mi][ni][q] = 0.f;

    for (int kb = 0; kb < K; kb += 64) {
        // load A tile: 128 rows x 64 halves (16B per thread-iter)
        #pragma unroll
        for (int i = 0; i < 4; i++) {
            int f = tid + i * 256;                  // 0..1023
            int r = f >> 3, c8 = (f & 7) * 8;       // 8 halves per thread
            int grow = row0 + r;
            uint4 v = make_uint4(0u, 0u, 0u, 0u);
            if (grow < M) v = *(const uint4*)(Xh + (size_t)grow * K + kb + c8);
            *(uint4*)(As + r * 72 + c8) = v;
        }
        // load B tile: 128 n-rows x 64 halves
        #pragma unroll
        for (int i = 0; i < 4; i++) {
            int f = tid + i * 256;
            int r = f >> 3, c8 = (f & 7) * 8;
            uint4 v = *(const uint4*)(WT + (size_t)(col0 + r) * K + kb + c8);
            *(uint4*)(Bs + r * 72 + c8) = v;
        }
        __syncthreads();
        #pragma unroll
        for (int kk = 0; kk < 4; kk++) {
            const int kc = kk * 16;
            unsigned a[2][4];
            #pragma unroll
            for (int mi = 0; mi < 2; mi++) {
                int rb = wm * 32 + mi * 16;
                a[mi][0] = *(const unsigned*)(As + (rb + gid    ) * 72 + kc + tig * 2);
                a[mi][1] = *(const unsigned*)(As + (rb + gid + 8) * 72 + kc + tig * 2);
                a[mi][2] = *(const unsigned*)(As + (rb + gid    ) * 72 + kc + 8 + tig * 2);
                a[mi][3] = *(const unsigned*)(As + (rb + gid + 8) * 72 + kc + 8 + tig * 2);
            }
            unsigned b[8][2];
            #pragma unroll
            for (int ni = 0; ni < 8; ni++) {
                int cb = wn * 64 + ni * 8 + gid;
                b[ni][0] = *(const unsigned*)(Bs + cb * 72 + kc + tig * 2);
                b[ni][1] = *(const unsigned*)(Bs + cb * 72 + kc + 8 + tig * 2);
            }
            #pragma unroll
            for (int mi = 0; mi < 2; mi++)
                #pragma unroll
                for (int ni = 0; ni < 8; ni++)
                    asm volatile(
                        "mma.sync.aligned.m16n8k16.row.col.f32.f16.f16.f32 "
                        "{%0,%1,%2,%3}, {%4,%5,%6,%7}, {%8,%9}, {%0,%1,%2,%3};\n"
                        : "+f"(acc[mi][ni][0]), "+f"(acc[mi][ni][1]),
                          "+f"(acc[mi][ni][2]), "+f"(acc[mi][ni][3])
                        : "r"(a[mi][0]), "r"(a[mi][1]), "r"(a[mi][2]), "r"(a[mi][3]),
                          "r"(b[ni][0]), "r"(b[ni][1]));
        }
        __syncthreads();
    }
    #pragma unroll
    for (int mi = 0; mi < 2; mi++) {
        int r0 = row0 + wm * 32 + mi * 16 + gid;
        int r1 = r0 + 8;
        #pragma unroll
        for (int ni = 0; ni < 8; ni++) {
            int lc = wn * 64 + ni * 8 + tig * 2;   // local col in [0,128)
            if (MODE == 0) {
                float b0 = bias[lc], b1 = bias[lc + 1];
                float v0 = acc[mi][ni][0] + b0, v1 = acc[mi][ni][1] + b1;
                float v2 = acc[mi][ni][2] + b0, v3 = acc[mi][ni][3] + b1;
                if (r0 < M) {
                    *(float2*)(Cx + (size_t)r0 * 128 + lc) = make_float2(v0, v1);
                    *(__half2*)(Cxh + (size_t)r0 * 128 + lc) = __floats2half2_rn(v0, v1);
                }
                if (r1 < M) {
                    *(float2*)(Cx + (size_t)r1 * 128 + lc) = make_float2(v2, v3);
                    *(__half2*)(Cxh + (size_t)r1 * 128 + lc) = __floats2half2_rn(v2, v3);
                }
            } else {
                __half* dst = (blockIdx.y == 0) ? Y1h : Y2h;
                if (r0 < M)
                    *(__half2*)(dst + (size_t)r0 * 128 + lc) =
                        __floats2half2_rn(acc[mi][ni][0], acc[mi][ni][1]);
                if (r1 < M)
                    *(__half2*)(dst + (size_t)r1 * 128 + lc) =
                        __floats2half2_rn(acc[mi][ni][2], acc[mi][ni][3]);
            }
        }
    }
}

// ---------------- cluster pooling (fp16 x) + pr GEMV fused ----------------
__global__ void k_poolpr(const __half* __restrict__ xh, const int* __restrict__ coff,
                         const int* __restrict__ cnodes, const float* __restrict__ tr,
                         const float* __restrict__ W_u, float* __restrict__ pr) {
    int c = blockIdx.x;
    int t = threadIdx.x;            // 256
    int col = t & 127, sub = t >> 7;
    int beg = coff[c], end = coff[c + 1];
    float acc = 0.f;
    for (int i = beg + sub; i < end; i += 2) {
        int nd = __ldg(&cnodes[i]);
        acc += __half2float(__ldg(&xh[(size_t)nd * 128 + col]));
    }
    __shared__ float red[256];
    __shared__ float prow[128];
    red[t] = acc; __syncthreads();
    if (t < 128) {
        int cnt = end - beg;
        float scale = tr[c] / (float)(cnt > 1 ? cnt : 1);
        prow[t] = (red[t] + red[t + 128]) * scale;
    }
    __syncthreads();
    if (t < 128) {
        float a = 0.f;
        #pragma unroll 8
        for (int k = 0; k < 128; k++) a += prow[k] * W_u[(256 + k) * 128 + t];
        pr[c * 128 + t] = a;
    }
}

// ---------------- fused fp16 edge aggregation + node update (warp per node) ----------------
__global__ void k_aggupd(const __half* __restrict__ Y1, const __half* __restrict__ Y2,
                         const int* __restrict__ rowptr, const int* __restrict__ csr,
                         const float* __restrict__ pr, const int* __restrict__ ccA,
                         const float* __restrict__ cvec, const float* __restrict__ b_u,
                         const float* __restrict__ A, const float* __restrict__ x_in,
                         float* __restrict__ x_out, __half* __restrict__ xh_out, int n) {
    int w = (blockIdx.x * blockDim.x + threadIdx.x) >> 5;
    int lane = threadIdx.x & 31;
    if (w >= n) return;
    int beg = rowptr[w], end = rowptr[w + 1];
    float4 a0 = make_float4(0.f, 0.f, 0.f, 0.f);
    float4 a1 = a0, a2 = a0, a3 = a0;
    for (int base = beg; base < end; base += 32) {
        int m = min(32, end - base);
        int sv = (lane < m) ? __ldg(&csr[base + lane]) : 0;
        int j = 0;
        for (; j + 4 <= m; j += 4) {
            int s0 = __shfl_sync(0xffffffffu, sv, j);
            int s1 = __shfl_sync(0xffffffffu, sv, j + 1);
            int s2 = __shfl_sync(0xffffffffu, sv, j + 2);
            int s3 = __shfl_sync(0xffffffffu, sv, j + 3);
            uint2 r0 = __ldg((const uint2*)(Y2 + (size_t)s0 * 128 + lane * 4));
            uint2 r1 = __ldg((const uint2*)(Y2 + (size_t)s1 * 128 + lane * 4));
            uint2 r2 = __ldg((const uint2*)(Y2 + (size_t)s2 * 128 + lane * 4));
            uint2 r3 = __ldg((const uint2*)(Y2 + (size_t)s3 * 128 + lane * 4));
            float2 p, q;
            p = __half22float2(*(__half2*)&r0.x); q = __half22float2(*(__half2*)&r0.y);
            a0.x += p.x; a0.y += p.y; a0.z += q.x; a0.w += q.y;
            p = __half22float2(*(__half2*)&r1.x); q = __half22float2(*(__half2*)&r1.y);
            a1.x += p.x; a1.y += p.y; a1.z += q.x; a1.w += q.y;
            p = __half22float2(*(__half2*)&r2.x); q = __half22float2(*(__half2*)&r2.y);
            a2.x += p.x; a2.y += p.y; a2.z += q.x; a2.w += q.y;
            p = __half22float2(*(__half2*)&r3.x); q = __half22float2(*(__half2*)&r3.y);
            a3.x += p.x; a3.y += p.y; a3.z += q.x; a3.w += q.y;
        }
        for (; j < m; j++) {
            int s0 = __shfl_sync(0xffffffffu, sv, j);
            uint2 r0 = __ldg((const uint2*)(Y2 + (size_t)s0 * 128 + lane * 4));
            float2 p = __half22float2(*(__half2*)&r0.x);
            float2 q = __half22float2(*(__half2*)&r0.y);
            a0.x += p.x; a0.y += p.y; a0.z += q.x; a0.w += q.y;
        }
    }
    float4 s = make_float4(a0.x + a1.x + a2.x + a3.x,
                           a0.y + a1.y + a2.y + a3.y,
                           a0.z + a1.z + a2.z + a3.z,
                           a0.w + a1.w + a2.w + a3.w);
    int deg = end - beg;
    if (deg > 0) {
        float4 cv = *(const float4*)(cvec + lane * 4);
        float inv = 1.0f / (float)deg;
        s.x = s.x * inv + cv.x; s.y = s.y * inv + cv.y;
        s.z = s.z * inv + cv.z; s.w = s.w * inv + cv.w;
    } else {
        // fixup: subtract x@A so that Y1 (= x@(Wu1+A)) collapses to x@Wu1
        float4 t = make_float4(0.f, 0.f, 0.f, 0.f);
        const float* xr = x_in + (size_t)w * 128;
        for (int k = 0; k < 128; k++) {
            float xv = xr[k];
            float4 av = __ldg((const float4*)(A + k * 128 + lane * 4));
            t.x += xv * av.x; t.y += xv * av.y; t.z += xv * av.z; t.w += xv * av.w;
        }
        s.x = -t.x; s.y = -t.y; s.z = -t.z; s.w = -t.w;
    }
    int c = ccA[w];
    uint2 y1r = __ldg((const uint2*)(Y1 + (size_t)w * 128 + lane * 4));
    float2 y1a = __half22float2(*(__half2*)&y1r.x);
    float2 y1b = __half22float2(*(__half2*)&y1r.y);
    float4 p  = __ldg((const float4*)(pr + c * 128 + lane * 4));
    float4 bu = *(const float4*)(b_u + lane * 4);
    float4 xi = __ldg((const float4*)(x_in + (size_t)w * 128 + lane * 4));
    float u0 = y1a.x + s.x + p.x + bu.x; u0 = (u0 > 0.f) ? u0 : 0.01f * u0;
    float u1 = y1a.y + s.y + p.y + bu.y; u1 = (u1 > 0.f) ? u1 : 0.01f * u1;
    float u2 = y1b.x + s.z + p.z + bu.z; u2 = (u2 > 0.f) ? u2 : 0.01f * u2;
    float u3 = y1b.y + s.w + p.w + bu.w; u3 = (u3 > 0.f) ? u3 : 0.01f * u3;
    float4 o = make_float4(xi.x + u0, xi.y + u1, xi.z + u2, xi.w + u3);
    *(float4*)(x_out + (size_t)w * 128 + lane * 4) = o;
    if (xh_out) {
        uint2 hv;
        *(__half2*)&hv.x = __floats2half2_rn(o.x, o.y);
        *(__half2*)&hv.y = __floats2half2_rn(o.z, o.w);
        *(uint2*)(xh_out + (size_t)w * 128 + lane * 4) = hv;
    }
}

// ---------------- launch ----------------
extern "C" void kernel_launch(void* const* d_in, const int* in_sizes, int n_in,
                              void* d_out, int out_size) {
    const float* cf    = (const float*)d_in[0];
    const float* slf   = (const float*)d_in[1];
    const float* z     = (const float*)d_in[2];
    const float* tr    = (const float*)d_in[3];
    const float* W_enc = (const float*)d_in[4];
    const float* b_enc = (const float*)d_in[5];
    const float* W_m   = (const float*)d_in[6];
    const float* b_m   = (const float*)d_in[7];
    const float* W_u   = (const float*)d_in[8];
    const float* b_u   = (const float*)d_in[9];
    const void*  e     = d_in[10];
    const void*  cc    = d_in[11];
    float* out = (float*)d_out;

    int n  = in_sizes[0] / 15;   // 100000
    int E  = in_sizes[10] / 2;   // 600000
    int bc = in_sizes[3];        // 384

    float *x, *A, *cvec, *pr;
    __half *xh, *Y1h, *Y2h, *xinh, *WcombT, *WencT;
    int *rowptr, *rowfill, *deg, *csr, *ccount, *coff, *cfill, *cnodes, *bsum, *bsumex;
    int *srcA, *dstA, *ccA, *flag;
    cudaGetSymbolAddress((void**)&x,      g_x);
    cudaGetSymbolAddress((void**)&xh,     g_xh);
    cudaGetSymbolAddress((void**)&Y1h,    g_Y1h);
    cudaGetSymbolAddress((void**)&Y2h,    g_Y2h);
    cudaGetSymbolAddress((void**)&xinh,   g_xinh);
    cudaGetSymbolAddress((void**)&WcombT, g_WcombT);
    cudaGetSymbolAddress((void**)&WencT,  g_WencT);
    cudaGetSymbolAddress((void**)&A,      g_A);
    cudaGetSymbolAddress((void**)&cvec,   g_cvec);
    cudaGetSymbolAddress((void**)&pr,     g_pr);
    cudaGetSymbolAddress((void**)&rowptr, g_rowptr);
    cudaGetSymbolAddress((void**)&rowfill,g_rowfill);
    cudaGetSymbolAddress((void**)&deg,    g_deg);
    cudaGetSymbolAddress((void**)&csr,    g_csr);
    cudaGetSymbolAddress((void**)&ccount, g_ccount);
    cudaGetSymbolAddress((void**)&coff,   g_coff);
    cudaGetSymbolAddress((void**)&cfill,  g_cfill);
    cudaGetSymbolAddress((void**)&cnodes, g_cnodes);
    cudaGetSymbolAddress((void**)&bsum,   g_bsum);
    cudaGetSymbolAddress((void**)&bsumex, g_bsumex);
    cudaGetSymbolAddress((void**)&srcA,   g_srcA);
    cudaGetSymbolAddress((void**)&dstA,   g_dstA);
    cudaGetSymbolAddress((void**)&ccA,    g_ccA);
    cudaGetSymbolAddress((void**)&flag,   g_flag);

    int bm = (n + 127) / 128;

    // ---- encoder path + weight folds ----
    k_wencT<<<128, 64>>>(W_enc, WencT);
    k_pack<<<((size_t)n * 64 + 255) / 256, 256>>>(cf, slf, z, xinh, n);
    k_gemmh<64, 0><<<dim3(bm, 1), 256>>>(xinh, WencT, b_enc, x, xh,
                                         nullptr, nullptr, n);
    k_foldT<<<128, 256>>>(W_m, W_u, WcombT, A);
    k_cvec<<<1, 128>>>(b_m, W_u, cvec);
    k_gemmh<128, 1><<<dim3(bm, 2), 256>>>(xh, WcombT, nullptr, nullptr, nullptr,
                                          Y1h, Y2h, n);

    // ---- CSR build ----
    k_detect<<<1, 32>>>((const int*)e, (const int*)cc, flag);
    k_zero<<<(n + 255) / 256, 256>>>(deg, ccount, n, bc);
    k_convhist<<<(E + 255) / 256, 256>>>(e, cc, srcA, dstA, ccA, flag, deg, ccount, E, n);
    int nb = (n + 4095) / 4096;
    k_scan_blocks<<<nb, 1024>>>(deg, rowptr, bsum, n);
    k_scan_small<<<1, 1024>>>(bsum, bsumex, nullptr, nb, 0);
    k_addoff<<<(n + 1023) / 1024, 1024>>>(rowptr, rowfill, bsumex, n, E);
    k_scan_small<<<1, 1024>>>(ccount, coff, cfill, bc, 1);
    k_scatter<<<(E + 255) / 256, 256>>>(srcA, dstA, ccA, rowfill, csr, cfill, cnodes, E, n);

    // ---- 3 GNN layers (layer-1 GEMM already issued above) ----
    int gblocks = ((size_t)n * 32 + 255) / 256;
    for (int l = 0; l < 3; l++) {
        if (l > 0)
            k_gemmh<128, 1><<<dim3(bm, 2), 256>>>(xh, WcombT, nullptr, nullptr, nullptr,
                                                  Y1h, Y2h, n);
        k_poolpr<<<bc, 256>>>(xh, coff, cnodes, tr, W_u, pr);
        float* xo = (l == 2) ? out : x;
        __half* xho = (l == 2) ? nullptr : xh;
        k_aggupd<<<gblocks, 256>>>(Y1h, Y2h, rowptr, csr, pr, ccA, cvec,
                                   b_u, A, x, xo, xho, n);
    }
}

// round 17
// speedup vs baseline: 1.6820x; 1.0501x over previous
#include <cuda_runtime.h>
#include <cuda_fp16.h>
#include <cstdint>

#define NMAX   100000
#define EMAX   600000
#define HDIM   128
#define BCMAX  384

// ---------------- static scratch (no allocations allowed) ----------------
__device__ float  g_x    [NMAX * HDIM];     // node features fp32 (residual-exact)
__device__ __half g_xh   [NMAX * HDIM];     // node features fp16 (GEMM A / pool)
__device__ __half g_Y1h  [NMAX * HDIM];     // x @ (Wu1 + A)   (fp16)
__device__ __half g_Y2h  [NMAX * HDIM];     // x @ B           (fp16, gathered)
__device__ __half g_xinh [NMAX * 64];       // packed encoder input fp16 (48->64 pad)
__device__ __half g_WcombT[256 * 128];      // transposed [n][k]: n<128 Wu1+A ; n>=128 B
__device__ __half g_WencT [128 * 64];       // transposed padded encoder weight [n][k]
__device__ float  g_A    [128 * 128];       // Wm_i @ Wu2 fp32 (deg==0 fixup)
__device__ float  g_cvec [128];             // b_m @ Wu2
__device__ float  g_pr   [BCMAX * HDIM];    // pooled_scaled @ Wu3
__device__ int    g_rowptr[NMAX + 1];
__device__ int    g_rowfill[NMAX];
__device__ int    g_deg  [NMAX];
__device__ int    g_csr  [EMAX];
__device__ int    g_ccount[BCMAX];
__device__ int    g_coff [BCMAX + 1];
__device__ int    g_cfill[BCMAX];
__device__ int    g_cnodes[NMAX];
__device__ int    g_bsum [64];
__device__ int    g_bsumex[64];
__device__ int    g_srcA [EMAX];
__device__ int    g_dstA [EMAX];
__device__ int    g_ccA  [NMAX];
__device__ int    g_flag [2];

// ---------------- cp.async helpers ----------------
__device__ __forceinline__ void cpasync16(uint32_t saddr, const void* g, bool pred) {
    int sz = pred ? 16 : 0;
    asm volatile("cp.async.ca.shared.global [%0], [%1], 16, %2;\n"
                 :: "r"(saddr), "l"(g), "r"(sz));
}
__device__ __forceinline__ void cp_commit() {
    asm volatile("cp.async.commit_group;\n");
}
template<int N>
__device__ __forceinline__ void cp_wait() {
    asm volatile("cp.async.wait_group %0;\n" :: "n"(N));
}

// ---------------- dtype detection ----------------
__global__ void k_detect(const int* __restrict__ e32, const int* __restrict__ c32,
                         int* flag) {
    int t = threadIdx.x;
    int ok_e = 1, ok_c = 1;
    for (int i = t; i < 256; i += 32) {
        ok_e &= (e32[2 * i + 1] == 0);
        ok_c &= (c32[2 * i + 1] == 0);
    }
    ok_e = __all_sync(0xffffffffu, ok_e);
    ok_c = __all_sync(0xffffffffu, ok_c);
    if (t == 0) { flag[0] = ok_e; flag[1] = ok_c; }
}

__global__ void k_zero(int* deg, int* ccount, int n, int bc) {
    int i = blockIdx.x * blockDim.x + threadIdx.x;
    if (i < n)  deg[i] = 0;
    if (i < bc) ccount[i] = 0;
}

__global__ void k_convhist(const void* __restrict__ e, const void* __restrict__ cc,
                           int* __restrict__ srcA, int* __restrict__ dstA,
                           int* __restrict__ ccA, const int* __restrict__ flag,
                           int* deg, int* ccount, int E, int n) {
    int i = blockIdx.x * blockDim.x + threadIdx.x;
    int f0 = flag[0], f1 = flag[1];
    if (i < E) {
        int s, d;
        if (f0) {
            const long long* e64 = (const long long*)e;
            s = (int)e64[i]; d = (int)e64[(size_t)E + i];
        } else {
            const int* e32 = (const int*)e;
            s = e32[i]; d = e32[E + i];
        }
        if ((unsigned)s >= (unsigned)n) s = 0;
        if ((unsigned)d >= (unsigned)n) d = 0;
        srcA[i] = s; dstA[i] = d;
        atomicAdd(&deg[d], 1);
    }
    if (i < n) {
        int c = f1 ? (int)((const long long*)cc)[i] : ((const int*)cc)[i];
        if ((unsigned)c >= (unsigned)BCMAX) c = 0;
        ccA[i] = c;
        atomicAdd(&ccount[c], 1);
    }
}

__global__ void k_scan_blocks(const int* __restrict__ in, int* __restrict__ out,
                              int* __restrict__ bsum, int n) {
    __shared__ int sm[1024];
    int t = threadIdx.x;
    int base = blockIdx.x * 4096 + t * 4;
    int v0 = (base + 0 < n) ? in[base + 0] : 0;
    int v1 = (base + 1 < n) ? in[base + 1] : 0;
    int v2 = (base + 2 < n) ? in[base + 2] : 0;
    int v3 = (base + 3 < n) ? in[base + 3] : 0;
    int tot = v0 + v1 + v2 + v3;
    sm[t] = tot; __syncthreads();
    for (int off = 1; off < 1024; off <<= 1) {
        int add = (t >= off) ? sm[t - off] : 0;
        __syncthreads();
        sm[t] += add;
        __syncthreads();
    }
    if (t == 1023) bsum[blockIdx.x] = sm[1023];
    int run = sm[t] - tot;
    if (base + 0 < n) out[base + 0] = run; run += v0;
    if (base + 1 < n) out[base + 1] = run; run += v1;
    if (base + 2 < n) out[base + 2] = run; run += v2;
    if (base + 3 < n) out[base + 3] = run;
}

__global__ void k_scan_small(const int* __restrict__ in, int* __restrict__ out,
                             int* __restrict__ fill, int n, int writeTotal) {
    __shared__ int sm[1024];
    int t = threadIdx.x;
    int v = (t < n) ? in[t] : 0;
    sm[t] = v; __syncthreads();
    for (int off = 1; off < 1024; off <<= 1) {
        int add = (t >= off) ? sm[t - off] : 0;
        __syncthreads();
        sm[t] += add;
        __syncthreads();
    }
    if (t < n) {
        int ex = sm[t] - v;
        out[t] = ex;
        if (fill) fill[t] = ex;
    }
    if (writeTotal && t == 1023) out[n] = sm[1023];
}

__global__ void k_addoff(int* rowptr, int* rowfill, const int* bsumex, int n, int total) {
    int i = blockIdx.x * blockDim.x + threadIdx.x;
    if (i < n) {
        int v = rowptr[i] + bsumex[i >> 12];
        rowptr[i] = v;
        rowfill[i] = v;
    }
    if (i == 0) rowptr[n] = total;
}

__global__ void k_scatter(const int* __restrict__ srcA, const int* __restrict__ dstA,
                          const int* __restrict__ ccA,
                          int* rowfill, int* csr, int* cfill, int* cnodes, int E, int n) {
    int i = blockIdx.x * blockDim.x + threadIdx.x;
    if (i < E) {
        int pos = atomicAdd(&rowfill[dstA[i]], 1);
        if ((unsigned)pos < (unsigned)EMAX) csr[pos] = srcA[i];
    }
    if (i < n) {
        int pos = atomicAdd(&cfill[ccA[i]], 1);
        if ((unsigned)pos < (unsigned)NMAX) cnodes[pos] = i;
    }
}

// ---------------- fused weight prep (foldT + cvec + wencT in one launch) ----------------
// blocks 0-127: WcombT/A fold for k=blockIdx.x
// block 128:    cvec
// blocks 129+:  WencT
__global__ void k_prep(const float* __restrict__ W_enc, const float* __restrict__ W_m,
                       const float* __restrict__ W_u, const float* __restrict__ b_m,
                       __half* __restrict__ WcombT, __half* __restrict__ WencT,
                       float* __restrict__ A, float* __restrict__ cvec) {
    int b = blockIdx.x;
    int t = threadIdx.x;   // 256
    if (b < 128) {
        int k = b;
        __shared__ float wi[128], wj[128];
        if (t < 128) {
            wi[t] = W_m[k * 128 + t];
            wj[t] = W_m[(128 + k) * 128 + t];
        }
        __syncthreads();
        if (t < 128) {
            float acc = 0.f;
            #pragma unroll 8
            for (int q = 0; q < 128; q++) acc += wi[q] * W_u[(128 + q) * 128 + t];
            A[k * 128 + t] = acc;
            WcombT[t * 128 + k] = __float2half(W_u[k * 128 + t] + acc);
        } else {
            int j = t - 128;
            float acc = 0.f;
            #pragma unroll 8
            for (int q = 0; q < 128; q++) acc += wj[q] * W_u[(128 + q) * 128 + j];
            WcombT[(128 + j) * 128 + k] = __float2half(acc);
        }
    } else if (b == 128) {
        if (t < 128) {
            float acc = 0.f;
            #pragma unroll 8
            for (int k = 0; k < 128; k++) acc += b_m[k] * W_u[(128 + k) * 128 + t];
            cvec[t] = acc;
        }
    } else {
        int idx = (b - 129) * 256 + t;      // 0..8191
        if (idx < 128 * 64) {
            int nn = idx >> 6, k = idx & 63;
            WencT[idx] = __float2half((k < 48) ? W_enc[k * 128 + nn] : 0.f);
        }
    }
}

__global__ void k_pack(const float* __restrict__ cf, const float* __restrict__ slf,
                       const float* __restrict__ z, __half* __restrict__ xinh, int n) {
    int i = blockIdx.x * blockDim.x + threadIdx.x;
    if (i >= n * 64) return;
    int nd = i >> 6, c = i & 63;
    float v;
    if (c < 15)       v = cf[nd * 15 + c];
    else if (c == 15) v = slf[nd];
    else if (c < 48)  v = z[nd * 32 + (c - 16)];
    else              v = 0.f;
    xinh[i] = __float2half(v);
}

// ---------------- fp16 HMMA GEMM, cp.async double-buffered over 32-wide K chunks ----
// WT is [NC][K] n-major fp16. mma.m16n8k16 f32.f16.f16.f32.
// MODE 0 (encoder): NC=128, out = fp32 x + fp16 xh, bias added.
// MODE 1 (layer):   NC=256, blockIdx.y picks col block: 0 -> Y1h, 1 -> Y2h.
template<int K, int MODE>
__global__ __launch_bounds__(256) void k_gemmh(
    const __half* __restrict__ Xh, const __half* __restrict__ WT,
    const float* __restrict__ bias,
    float* __restrict__ Cx, __half* __restrict__ Cxh,
    __half* __restrict__ Y1h, __half* __restrict__ Y2h, int M) {
    constexpr int NKB = K / 32;
    __shared__ __half As[2][128 * 40];
    __shared__ __half Bs[2][128 * 40];
    const int tid = threadIdx.x;
    const int lane = tid & 31, wid = tid >> 5;
    const int wm = wid & 3, wn = wid >> 2;          // wm 0-3 (M), wn 0-1 (N)
    const int gid = lane >> 2, tig = lane & 3;
    const int row0 = blockIdx.x * 128;
    const int col0 = (MODE == 1) ? blockIdx.y * 128 : 0;
    // per-thread load coords: 512 uint4 per tile, 256 threads -> 2 each
    const int r0l = tid >> 2,            c0l = (tid & 3) * 8;          // i=0
    const int r1l = (tid + 256) >> 2,    c1l = ((tid + 256) & 3) * 8;  // i=1
    const bool a0ok = (row0 + r0l) < M, a1ok = (row0 + r1l) < M;
    uint32_t sA0[2], sA1[2], sB0[2], sB1[2];
    #pragma unroll
    for (int b = 0; b < 2; b++) {
        sA0[b] = (uint32_t)__cvta_generic_to_shared(&As[b][r0l * 40 + c0l]);
        sA1[b] = (uint32_t)__cvta_generic_to_shared(&As[b][r1l * 40 + c1l]);
        sB0[b] = (uint32_t)__cvta_generic_to_shared(&Bs[b][r0l * 40 + c0l]);
        sB1[b] = (uint32_t)__cvta_generic_to_shared(&Bs[b][r1l * 40 + c1l]);
    }

    float acc[2][8][4];
    #pragma unroll
    for (int mi = 0; mi < 2; mi++)
        #pragma unroll
        for (int ni = 0; ni < 8; ni++)
            #pragma unroll
            for (int q = 0; q < 4; q++) acc[mi][ni][q] = 0.f;

    // prologue: load chunk 0 into buffer 0
    {
        int kb = 0;
        cpasync16(sA0[0], Xh + (size_t)(row0 + r0l) * K + kb + c0l, a0ok);
        cpasync16(sA1[0], Xh + (size_t)(row0 + r1l) * K + kb + c1l, a1ok);
        cpasync16(sB0[0], WT + (size_t)(col0 + r0l) * K + kb + c0l, true);
        cpasync16(sB1[0], WT + (size_t)(col0 + r1l) * K + kb + c1l, true);
        cp_commit();
    }

    #pragma unroll
    for (int it = 0; it < NKB; it++) {
        if (it + 1 < NKB) {
            int kb = (it + 1) * 32;
            int nb = (it + 1) & 1;
            cpasync16(sA0[nb], Xh + (size_t)(row0 + r0l) * K + kb + c0l, a0ok);
            cpasync16(sA1[nb], Xh + (size_t)(row0 + r1l) * K + kb + c1l, a1ok);
            cpasync16(sB0[nb], WT + (size_t)(col0 + r0l) * K + kb + c0l, true);
            cpasync16(sB1[nb], WT + (size_t)(col0 + r1l) * K + kb + c1l, true);
            cp_commit();
            cp_wait<1>();
        } else {
            cp_wait<0>();
        }
        __syncthreads();
        const int buf = it & 1;
        const __half* Ab = As[buf];
        const __half* Bb = Bs[buf];
        #pragma unroll
        for (int kk = 0; kk < 2; kk++) {
            const int kc = kk * 16;
            unsigned a[2][4];
            #pragma unroll
            for (int mi = 0; mi < 2; mi++) {
                int rb = wm * 32 + mi * 16;
                a[mi][0] = *(const unsigned*)(Ab + (rb + gid    ) * 40 + kc + tig * 2);
                a[mi][1] = *(const unsigned*)(Ab + (rb + gid + 8) * 40 + kc + tig * 2);
                a[mi][2] = *(const unsigned*)(Ab + (rb + gid    ) * 40 + kc + 8 + tig * 2);
                a[mi][3] = *(const unsigned*)(Ab + (rb + gid + 8) * 40 + kc + 8 + tig * 2);
            }
            unsigned b[8][2];
            #pragma unroll
            for (int ni = 0; ni < 8; ni++) {
                int cb = wn * 64 + ni * 8 + gid;
                b[ni][0] = *(const unsigned*)(Bb + cb * 40 + kc + tig * 2);
                b[ni][1] = *(const unsigned*)(Bb + cb * 40 + kc + 8 + tig * 2);
            }
            #pragma unroll
            for (int mi = 0; mi < 2; mi++)
                #pragma unroll
                for (int ni = 0; ni < 8; ni++)
                    asm volatile(
                        "mma.sync.aligned.m16n8k16.row.col.f32.f16.f16.f32 "
                        "{%0,%1,%2,%3}, {%4,%5,%6,%7}, {%8,%9}, {%0,%1,%2,%3};\n"
                        : "+f"(acc[mi][ni][0]), "+f"(acc[mi][ni][1]),
                          "+f"(acc[mi][ni][2]), "+f"(acc[mi][ni][3])
                        : "r"(a[mi][0]), "r"(a[mi][1]), "r"(a[mi][2]), "r"(a[mi][3]),
                          "r"(b[ni][0]), "r"(b[ni][1]));
        }
        __syncthreads();
    }

    #pragma unroll
    for (int mi = 0; mi < 2; mi++) {
        int r0 = row0 + wm * 32 + mi * 16 + gid;
        int r1 = r0 + 8;
        #pragma unroll
        for (int ni = 0; ni < 8; ni++) {
            int lc = wn * 64 + ni * 8 + tig * 2;   // local col in [0,128)
            if (MODE == 0) {
                float b0 = bias[lc], b1 = bias[lc + 1];
                float v0 = acc[mi][ni][0] + b0, v1 = acc[mi][ni][1] + b1;
                float v2 = acc[mi][ni][2] + b0, v3 = acc[mi][ni][3] + b1;
                if (r0 < M) {
                    *(float2*)(Cx + (size_t)r0 * 128 + lc) = make_float2(v0, v1);
                    *(__half2*)(Cxh + (size_t)r0 * 128 + lc) = __floats2half2_rn(v0, v1);
                }
                if (r1 < M) {
                    *(float2*)(Cx + (size_t)r1 * 128 + lc) = make_float2(v2, v3);
                    *(__half2*)(Cxh + (size_t)r1 * 128 + lc) = __floats2half2_rn(v2, v3);
                }
            } else {
                __half* dst = (blockIdx.y == 0) ? Y1h : Y2h;
                if (r0 < M)
                    *(__half2*)(dst + (size_t)r0 * 128 + lc) =
                        __floats2half2_rn(acc[mi][ni][0], acc[mi][ni][1]);
                if (r1 < M)
                    *(__half2*)(dst + (size_t)r1 * 128 + lc) =
                        __floats2half2_rn(acc[mi][ni][2], acc[mi][ni][3]);
            }
        }
    }
}

// ---------------- cluster pooling (fp16 x) + pr GEMV fused ----------------
__global__ void k_poolpr(const __half* __restrict__ xh, const int* __restrict__ coff,
                         const int* __restrict__ cnodes, const float* __restrict__ tr,
                         const float* __restrict__ W_u, float* __restrict__ pr) {
    int c = blockIdx.x;
    int t = threadIdx.x;            // 256
    int col = t & 127, sub = t >> 7;
    int beg = coff[c], end = coff[c + 1];
    float acc = 0.f;
    for (int i = beg + sub; i < end; i += 2) {
        int nd = __ldg(&cnodes[i]);
        acc += __half2float(__ldg(&xh[(size_t)nd * 128 + col]));
    }
    __shared__ float red[256];
    __shared__ float prow[128];
    red[t] = acc; __syncthreads();
    if (t < 128) {
        int cnt = end - beg;
        float scale = tr[c] / (float)(cnt > 1 ? cnt : 1);
        prow[t] = (red[t] + red[t + 128]) * scale;
    }
    __syncthreads();
    if (t < 128) {
        float a = 0.f;
        #pragma unroll 8
        for (int k = 0; k < 128; k++) a += prow[k] * W_u[(256 + k) * 128 + t];
        pr[c * 128 + t] = a;
    }
}

// ---------------- fused fp16 edge aggregation + node update (warp per node) ----------------
__global__ void k_aggupd(const __half* __restrict__ Y1, const __half* __restrict__ Y2,
                         const int* __restrict__ rowptr, const int* __restrict__ csr,
                         const float* __restrict__ pr, const int* __restrict__ ccA,
                         const float* __restrict__ cvec, const float* __restrict__ b_u,
                         const float* __restrict__ A, const float* __restrict__ x_in,
                         float* __restrict__ x_out, __half* __restrict__ xh_out, int n) {
    int w = (blockIdx.x * blockDim.x + threadIdx.x) >> 5;
    int lane = threadIdx.x & 31;
    if (w >= n) return;
    int beg = rowptr[w], end = rowptr[w + 1];
    float4 a0 = make_float4(0.f, 0.f, 0.f, 0.f);
    float4 a1 = a0, a2 = a0, a3 = a0;
    for (int base = beg; base < end; base += 32) {
        int m = min(32, end - base);
        int sv = (lane < m) ? __ldg(&csr[base + lane]) : 0;
        int j = 0;
        for (; j + 4 <= m; j += 4) {
            int s0 = __shfl_sync(0xffffffffu, sv, j);
            int s1 = __shfl_sync(0xffffffffu, sv, j + 1);
            int s2 = __shfl_sync(0xffffffffu, sv, j + 2);
            int s3 = __shfl_sync(0xffffffffu, sv, j + 3);
            uint2 r0 = __ldg((const uint2*)(Y2 + (size_t)s0 * 128 + lane * 4));
            uint2 r1 = __ldg((const uint2*)(Y2 + (size_t)s1 * 128 + lane * 4));
            uint2 r2 = __ldg((const uint2*)(Y2 + (size_t)s2 * 128 + lane * 4));
            uint2 r3 = __ldg((const uint2*)(Y2 + (size_t)s3 * 128 + lane * 4));
            float2 p, q;
            p = __half22float2(*(__half2*)&r0.x); q = __half22float2(*(__half2*)&r0.y);
            a0.x += p.x; a0.y += p.y; a0.z += q.x; a0.w += q.y;
            p = __half22float2(*(__half2*)&r1.x); q = __half22float2(*(__half2*)&r1.y);
            a1.x += p.x; a1.y += p.y; a1.z += q.x; a1.w += q.y;
            p = __half22float2(*(__half2*)&r2.x); q = __half22float2(*(__half2*)&r2.y);
            a2.x += p.x; a2.y += p.y; a2.z += q.x; a2.w += q.y;
            p = __half22float2(*(__half2*)&r3.x); q = __half22float2(*(__half2*)&r3.y);
            a3.x += p.x; a3.y += p.y; a3.z += q.x; a3.w += q.y;
        }
        for (; j < m; j++) {
            int s0 = __shfl_sync(0xffffffffu, sv, j);
            uint2 r0 = __ldg((const uint2*)(Y2 + (size_t)s0 * 128 + lane * 4));
            float2 p = __half22float2(*(__half2*)&r0.x);
            float2 q = __half22float2(*(__half2*)&r0.y);
            a0.x += p.x; a0.y += p.y; a0.z += q.x; a0.w += q.y;
        }
    }
    float4 s = make_float4(a0.x + a1.x + a2.x + a3.x,
                           a0.y + a1.y + a2.y + a3.y,
                           a0.z + a1.z + a2.z + a3.z,
                           a0.w + a1.w + a2.w + a3.w);
    int deg = end - beg;
    if (deg > 0) {
        float4 cv = *(const float4*)(cvec + lane * 4);
        float inv = 1.0f / (float)deg;
        s.x = s.x * inv + cv.x; s.y = s.y * inv + cv.y;
        s.z = s.z * inv + cv.z; s.w = s.w * inv + cv.w;
    } else {
        // fixup: subtract x@A so that Y1 (= x@(Wu1+A)) collapses to x@Wu1
        float4 t = make_float4(0.f, 0.f, 0.f, 0.f);
        const float* xr = x_in + (size_t)w * 128;
        for (int k = 0; k < 128; k++) {
            float xv = xr[k];
            float4 av = __ldg((const float4*)(A + k * 128 + lane * 4));
            t.x += xv * av.x; t.y += xv * av.y; t.z += xv * av.z; t.w += xv * av.w;
        }
        s.x = -t.x; s.y = -t.y; s.z = -t.z; s.w = -t.w;
    }
    int c = ccA[w];
    uint2 y1r = __ldg((const uint2*)(Y1 + (size_t)w * 128 + lane * 4));
    float2 y1a = __half22float2(*(__half2*)&y1r.x);
    float2 y1b = __half22float2(*(__half2*)&y1r.y);
    float4 p  = __ldg((const float4*)(pr + c * 128 + lane * 4));
    float4 bu = *(const float4*)(b_u + lane * 4);
    float4 xi = __ldg((const float4*)(x_in + (size_t)w * 128 + lane * 4));
    float u0 = y1a.x + s.x + p.x + bu.x; u0 = (u0 > 0.f) ? u0 : 0.01f * u0;
    float u1 = y1a.y + s.y + p.y + bu.y; u1 = (u1 > 0.f) ? u1 : 0.01f * u1;
    float u2 = y1b.x + s.z + p.z + bu.z; u2 = (u2 > 0.f) ? u2 : 0.01f * u2;
    float u3 = y1b.y + s.w + p.w + bu.w; u3 = (u3 > 0.f) ? u3 : 0.01f * u3;
    float4 o = make_float4(xi.x + u0, xi.y + u1, xi.z + u2, xi.w + u3);
    *(float4*)(x_out + (size_t)w * 128 + lane * 4) = o;
    if (xh_out) {
        uint2 hv;
        *(__half2*)&hv.x = __floats2half2_rn(o.x, o.y);
        *(__half2*)&hv.y = __floats2half2_rn(o.z, o.w);
        *(uint2*)(xh_out + (size_t)w * 128 + lane * 4) = hv;
    }
}

// ---------------- launch ----------------
extern "C" void kernel_launch(void* const* d_in, const int* in_sizes, int n_in,
                              void* d_out, int out_size) {
    const float* cf    = (const float*)d_in[0];
    const float* slf   = (const float*)d_in[1];
    const float* z     = (const float*)d_in[2];
    const float* tr    = (const float*)d_in[3];
    const float* W_enc = (const float*)d_in[4];
    const float* b_enc = (const float*)d_in[5];
    const float* W_m   = (const float*)d_in[6];
    const float* b_m   = (const float*)d_in[7];
    const float* W_u   = (const float*)d_in[8];
    const float* b_u   = (const float*)d_in[9];
    const void*  e     = d_in[10];
    const void*  cc    = d_in[11];
    float* out = (float*)d_out;

    int n  = in_sizes[0] / 15;   // 100000
    int E  = in_sizes[10] / 2;   // 600000
    int bc = in_sizes[3];        // 384

    float *x, *A, *cvec, *pr;
    __half *xh, *Y1h, *Y2h, *xinh, *WcombT, *WencT;
    int *rowptr, *rowfill, *deg, *csr, *ccount, *coff, *cfill, *cnodes, *bsum, *bsumex;
    int *srcA, *dstA, *ccA, *flag;
    cudaGetSymbolAddress((void**)&x,      g_x);
    cudaGetSymbolAddress((void**)&xh,     g_xh);
    cudaGetSymbolAddress((void**)&Y1h,    g_Y1h);
    cudaGetSymbolAddress((void**)&Y2h,    g_Y2h);
    cudaGetSymbolAddress((void**)&xinh,   g_xinh);
    cudaGetSymbolAddress((void**)&WcombT, g_WcombT);
    cudaGetSymbolAddress((void**)&WencT,  g_WencT);
    cudaGetSymbolAddress((void**)&A,      g_A);
    cudaGetSymbolAddress((void**)&cvec,   g_cvec);
    cudaGetSymbolAddress((void**)&pr,     g_pr);
    cudaGetSymbolAddress((void**)&rowptr, g_rowptr);
    cudaGetSymbolAddress((void**)&rowfill,g_rowfill);
    cudaGetSymbolAddress((void**)&deg,    g_deg);
    cudaGetSymbolAddress((void**)&csr,    g_csr);
    cudaGetSymbolAddress((void**)&ccount, g_ccount);
    cudaGetSymbolAddress((void**)&coff,   g_coff);
    cudaGetSymbolAddress((void**)&cfill,  g_cfill);
    cudaGetSymbolAddress((void**)&cnodes, g_cnodes);
    cudaGetSymbolAddress((void**)&bsum,   g_bsum);
    cudaGetSymbolAddress((void**)&bsumex, g_bsumex);
    cudaGetSymbolAddress((void**)&srcA,   g_srcA);
    cudaGetSymbolAddress((void**)&dstA,   g_dstA);
    cudaGetSymbolAddress((void**)&ccA,    g_ccA);
    cudaGetSymbolAddress((void**)&flag,   g_flag);

    int bm = (n + 127) / 128;

    // ---- launches 0-3: prep, pack, encoder GEMM, layer-1 GEMM (idx 3 = profiled) ----
    k_prep<<<161, 256>>>(W_enc, W_m, W_u, b_m, WcombT, WencT, A, cvec);        // 0
    k_pack<<<((size_t)n * 64 + 255) / 256, 256>>>(cf, slf, z, xinh, n);        // 1
    k_gemmh<64, 0><<<dim3(bm, 1), 256>>>(xinh, WencT, b_enc, x, xh,
                                         nullptr, nullptr, n);                 // 2
    k_gemmh<128, 1><<<dim3(bm, 2), 256>>>(xh, WcombT, nullptr, nullptr, nullptr,
                                          Y1h, Y2h, n);                        // 3 <- profiled

    // ---- CSR build ----
    k_detect<<<1, 32>>>((const int*)e, (const int*)cc, flag);
    k_zero<<<(n + 255) / 256, 256>>>(deg, ccount, n, bc);
    k_convhist<<<(E + 255) / 256, 256>>>(e, cc, srcA, dstA, ccA, flag, deg, ccount, E, n);
    int nb = (n + 4095) / 4096;
    k_scan_blocks<<<nb, 1024>>>(deg, rowptr, bsum, n);
    k_scan_small<<<1, 1024>>>(bsum, bsumex, nullptr, nb, 0);
    k_addoff<<<(n + 1023) / 1024, 1024>>>(rowptr, rowfill, bsumex, n, E);
    k_scan_small<<<1, 1024>>>(ccount, coff, cfill, bc, 1);
    k_scatter<<<(E + 255) / 256, 256>>>(srcA, dstA, ccA, rowfill, csr, cfill, cnodes, E, n);

    // ---- 3 GNN layers (layer-1 GEMM already issued above) ----
    int gblocks = ((size_t)n * 32 + 255) / 256;
    for (int l = 0; l < 3; l++) {
        if (l > 0)
            k_gemmh<128, 1><<<dim3(bm, 2), 256>>>(xh, WcombT, nullptr, nullptr, nullptr,
                                                  Y1h, Y2h, n);
        k_poolpr<<<bc, 256>>>(xh, coff, cnodes, tr, W_u, pr);
        float* xo = (l == 2) ? out : x;
        __half* xho = (l == 2) ? nullptr : xh;
        k_aggupd<<<gblocks, 256>>>(Y1h, Y2h, rowptr, csr, pr, ccA, cvec,
                                   b_u, A, x, xo, xho, n);
    }
}